// round 9
// baseline (speedup 1.0000x reference)
#include <cuda_runtime.h>
#include <math_constants.h>
#include <math.h>
#include <cstdint>

// Problem constants
#define S_LEN 2048
#define EMB   2048
#define NH    16
#define NKV   4
#define HD    128
#define FQKV  3072   // NH*HD + 2*NKV*HD
#define GK    2048   // K dim of BOTH projection GEMMs (compile-time)

// Scratch (device globals: no allocations allowed)
__device__ float g_qkv[S_LEN * FQKV];     // 25 MB (Q,K tf32-rounded by rope)
__device__ float g_ctx[S_LEN * EMB];      // 17 MB (tf32-rounded ctx)
__device__ float g_xr[S_LEN * EMB];       // 16 MB (tf32-rounded x)
__device__ float g_wqkvr[FQKV * EMB];     // 24 MB
__device__ float g_wdr[EMB * EMB];        // 16 MB
__device__ float g_vt[NKV * HD * S_LEN];  //  4 MB (V transposed, tf32-rounded)

// ---------------------------------------------------------------------------
// Helpers (plain sm_100: mma.sync tensor cores)
// ---------------------------------------------------------------------------
__device__ __forceinline__ uint32_t smem_u32(const void* p) {
    uint32_t a;
    asm("{ .reg .u64 t; cvta.to.shared.u64 t, %1; cvt.u32.u64 %0, t; }"
        : "=r"(a) : "l"(p));
    return a;
}

__device__ __forceinline__ float tf32r(float x) {
    uint32_t u;
    asm("cvt.rna.tf32.f32 %0, %1;" : "=r"(u) : "f"(x));
    return __uint_as_float(u);
}

// D += A(16x8,row) * B(8x8,col)  tf32, f32 accum
__device__ __forceinline__ void mma8(float* c, const uint32_t* a,
                                     uint32_t b0, uint32_t b1) {
    asm volatile(
        "mma.sync.aligned.m16n8k8.row.col.f32.tf32.tf32.f32 "
        "{%0,%1,%2,%3}, {%4,%5,%6,%7}, {%8,%9}, {%0,%1,%2,%3};\n"
        : "+f"(c[0]), "+f"(c[1]), "+f"(c[2]), "+f"(c[3])
        : "r"(a[0]), "r"(a[1]), "r"(a[2]), "r"(a[3]), "r"(b0), "r"(b1));
}

// byte offset of 16B granule (row, g) in an XOR-swizzled tile; gper granules/row
__device__ __forceinline__ uint32_t sw16(int row, int g, int gper) {
    return (uint32_t)(row * gper + (((g ^ row) & 7) | (g & ~7))) * 16;
}

// ldmatrix.x4 at a fully-resolved smem byte address
__device__ __forceinline__ void ldm4i(uint32_t* r, uint32_t addr) {
    asm volatile("ldmatrix.sync.aligned.m8n8.x4.shared.b16 {%0,%1,%2,%3}, [%4];"
                 : "=r"(r[0]), "=r"(r[1]), "=r"(r[2]), "=r"(r[3]) : "r"(addr));
}

// ldmatrix.x4 from an XOR-swizzled tile (smem byte base), 16-row x 8-f32-col.
__device__ __forceinline__ void ldm4s(uint32_t* r, uint32_t sbase,
                                      int row0, int col0, int gper) {
    int t = threadIdx.x & 31;
    int rr = row0 + (t & 15);
    int gc = (col0 >> 2) + (t >> 4);
    uint32_t addr = sbase + sw16(rr, gc, gper);
    ldm4i(r, addr);
}

// ldmatrix.x4 from a padded (unswizzled) f32 tile
__device__ __forceinline__ void ldm4(uint32_t* r, const float* base,
                                     int row0, int col0, int stride) {
    int t = threadIdx.x & 31;
    int rr = row0 + (t & 15);
    int cc = col0 + ((t >> 4) << 2);
    ldm4i(r, smem_u32(base + rr * stride + cc));
}

__device__ __forceinline__ void cpasync16(uint32_t dst, const float* src) {
    asm volatile("cp.async.cg.shared.global [%0], [%1], 16;" :: "r"(dst), "l"(src));
}
__device__ __forceinline__ void cpcommit() {
    asm volatile("cp.async.commit_group;");
}

// ---------------------------------------------------------------------------
// tf32 pre-round
// ---------------------------------------------------------------------------
__global__ void round_tf32_kernel(const float* __restrict__ in,
                                  float* __restrict__ out, int n4) {
    int i = blockIdx.x * blockDim.x + threadIdx.x;
    for (; i < n4; i += gridDim.x * blockDim.x) {
        float4 v = ((const float4*)in)[i];
        v.x = tf32r(v.x); v.y = tf32r(v.y); v.z = tf32r(v.z); v.w = tf32r(v.w);
        ((float4*)out)[i] = v;
    }
}

// ---------------------------------------------------------------------------
// tf32 mma GEMM, K hardcoded = 2048: C[m,n] = sum_k A[m,k]*B[n,k].
// Block 128x128, BK=32, 4 warps (64x64 warp tile), 2-stage cp.async,
// XOR-swizzled smem. All mainloop addresses are base-reg + immediate:
// global ptrs advance +32 floats/chunk; LDSM offsets are lane constants.
// ---------------------------------------------------------------------------
#define GEMM_SMEM 65536   // 2 stages x (A 16KB + B 16KB)

__global__ __launch_bounds__(128, 3) void gemm_mma(const float* __restrict__ A,
                                                   const float* __restrict__ B,
                                                   float* __restrict__ C, int N) {
    extern __shared__ float sm[];
    const uint32_t sb = smem_u32(sm);
    const int tid = threadIdx.x;
    const int lane = tid & 31;
    const int wid = tid >> 5;          // 0..3
    const int bm = blockIdx.y * 128;
    const int bn = blockIdx.x * 128;
    const int wm = (wid >> 1) * 64;
    const int wn = (wid & 1) * 64;

    // loader lanes: thread handles rows {tid>>3 + 16i}, granule g = tid&7.
    const float* aptr = A + (size_t)(bm + (tid >> 3)) * GK + (tid & 7) * 4;
    const float* bptr = B + (size_t)(bn + (tid >> 3)) * GK + (tid & 7) * 4;
    const uint32_t sda = sb +
        (uint32_t)((tid >> 3) * 128 + (((tid & 7) ^ ((tid >> 3) & 7)) * 16));

    // compute lanes: swizzle collapses to lane constants (row0 16-aligned)
    const int lx = lane & 7, hi = lane >> 4;
    uint32_t swv[4];
#pragma unroll
    for (int kk = 0; kk < 4; kk++)
        swv[kk] = (uint32_t)(((2 * kk + hi) ^ lx) * 16);
    const uint32_t aS = sb + (uint32_t)((lane & 15) * 128 + wm * 128);
    const uint32_t bS = sb + (uint32_t)((lane & 15) * 128 + wn * 128) + 16384;

    float acc[4][8][4];
#pragma unroll
    for (int i = 0; i < 4; i++)
#pragma unroll
        for (int j = 0; j < 8; j++)
#pragma unroll
            for (int q = 0; q < 4; q++) acc[i][j][q] = 0.f;

    auto issue = [&](uint32_t stoff) {
#pragma unroll
        for (int i = 0; i < 8; i++) {
            cpasync16(sda + stoff + i * 2048,         aptr + (size_t)i * 16 * GK);
            cpasync16(sda + stoff + 16384 + i * 2048, bptr + (size_t)i * 16 * GK);
        }
        cpcommit();
        aptr += 32; bptr += 32;
    };

    auto compute = [&](uint32_t stoff) {
#pragma unroll
        for (int kk = 0; kk < 4; kk++) {
            const uint32_t aa = aS + stoff + swv[kk];
            const uint32_t bb = bS + stoff + swv[kk];
            uint32_t a[4][4];
#pragma unroll
            for (int mf = 0; mf < 4; mf++) ldm4i(a[mf], aa + mf * 2048);
#pragma unroll
            for (int nf = 0; nf < 4; nf++) {
                uint32_t b[4];
                ldm4i(b, bb + nf * 2048);
#pragma unroll
                for (int mf = 0; mf < 4; mf++) {
                    mma8(acc[mf][2 * nf],     a[mf], b[0], b[2]);
                    mma8(acc[mf][2 * nf + 1], a[mf], b[1], b[3]);
                }
            }
        }
    };

    issue(0);                        // chunk 0 -> stage 0
#pragma unroll 1
    for (int c2 = 0; c2 < GK / 64; c2++) {   // 32 double-chunks
        issue(32768);                // chunk 2c2+1 -> stage 1
        asm volatile("cp.async.wait_group 1;");
        __syncthreads();
        compute(0);
        __syncthreads();
        if (c2 < GK / 64 - 1) {
            issue(0);                // chunk 2c2+2 -> stage 0
            asm volatile("cp.async.wait_group 1;");
        } else {
            asm volatile("cp.async.wait_group 0;");
        }
        __syncthreads();
        compute(32768);
        __syncthreads();
    }

#pragma unroll
    for (int mf = 0; mf < 4; mf++) {
        int r0 = bm + wm + mf * 16 + (lane >> 2);
#pragma unroll
        for (int nf = 0; nf < 8; nf++) {
            int cc = bn + wn + nf * 8 + 2 * (lane & 3);
            *(float2*)(C + (size_t)r0 * N + cc) =
                make_float2(acc[mf][nf][0], acc[mf][nf][1]);
            *(float2*)(C + (size_t)(r0 + 8) * N + cc) =
                make_float2(acc[mf][nf][2], acc[mf][nf][3]);
        }
    }
}

// ---------------------------------------------------------------------------
// RoPE in-place on Q,K heads of g_qkv; output tf32-rounded (feeds mma directly)
// ---------------------------------------------------------------------------
__global__ void rope_kernel() {
    int s    = blockIdx.x;
    int head = blockIdx.y;
    int i    = threadIdx.x;

    size_t off = (size_t)s * FQKV +
                 ((head < NH) ? (size_t)head * HD
                              : (size_t)NH * HD + (size_t)(head - NH) * HD);
    float* base = g_qkv + off;

    float inv_freq = expf(-(float)(2 * i) * (9.210340371976184f / 128.f));
    float ang = (float)s * inv_freq;
    float c, sn;
    sincosf(ang, &sn, &c);

    float x1 = base[i];
    float x2 = base[i + 64];
    base[i]      = tf32r(x1 * c - x2 * sn);
    base[i + 64] = tf32r(x2 * c + x1 * sn);
}

// ---------------------------------------------------------------------------
// V transpose: g_vt[kvh*HD + d][s] = tf32r(V[s][kvh][d])
// ---------------------------------------------------------------------------
__global__ void vtrans_kernel() {
    __shared__ float t[32][33];
    int kvh = blockIdx.z;
    int s0 = blockIdx.x * 32, d0 = blockIdx.y * 32;
    int tx = threadIdx.x, ty = threadIdx.y;   // 32 x 8
#pragma unroll
    for (int i = 0; i < 32; i += 8)
        t[ty + i][tx] =
            g_qkv[(size_t)(s0 + ty + i) * FQKV + (NH + NKV) * HD + kvh * HD + d0 + tx];
    __syncthreads();
#pragma unroll
    for (int i = 0; i < 32; i += 8)
        g_vt[((size_t)kvh * HD + d0 + ty + i) * S_LEN + s0 + tx] = tf32r(t[tx][ty + i]);
}

// ---------------------------------------------------------------------------
// Flash attention, mma tf32, fully cp.async-pipelined (identical to R8 pass).
// CTA: 128 q-rows x 1 head, 8 warps (16 q-rows each), k-tile 64.
// smem: Qs 128x128 sw (64K), Ks 2x64x128 sw (64K), Vt 128x64 sw (32K),
//       Ps 128x68 padded (34K) = 198656 B.
// ---------------------------------------------------------------------------
#define AQ_OFF 0
#define AK_OFF 65536
#define AV_OFF 131072
#define AP_F32 40960                 // Ps f32 index base (byte 163840)
#define ATT_SMEM 198656

__global__ __launch_bounds__(256, 1) void flash_attn_mma() {
    extern __shared__ float sm[];
    const uint32_t sb = smem_u32(sm);
    float* Ps = sm + AP_F32;

    const int tid = threadIdx.x;
    const int lane = tid & 31;
    const int w = tid >> 5;
    const int h = blockIdx.x;
    const int kvh = h >> 2;
    const int qt = (int)gridDim.y - 1 - (int)blockIdx.y;  // heavy first
    const int q0 = qt * 128;
    const float scale = 0.08838834764831845f;   // 1/sqrt(128)

    // prologue: Q + K(0) as one commit group
    {
#pragma unroll
        for (int i = 0; i < 16; i++) {
            int idx = i * 256 + tid;
            int row = idx >> 5;
            int g   = idx & 31;
            cpasync16(sb + AQ_OFF + sw16(row, g, 32),
                      g_qkv + (size_t)(q0 + row) * FQKV + h * HD + g * 4);
        }
#pragma unroll
        for (int i = 0; i < 8; i++) {
            int idx = i * 256 + tid;
            int row = idx >> 5;
            int g   = idx & 31;
            cpasync16(sb + AK_OFF + sw16(row, g, 32),
                      g_qkv + (size_t)(row) * FQKV + NH * HD + kvh * HD + g * 4);
        }
        cpcommit();
    }

    float m0 = -CUDART_INF_F, m1 = -CUDART_INF_F, l0 = 0.f, l1 = 0.f;
    float o[16][4];
#pragma unroll
    for (int f = 0; f < 16; f++)
#pragma unroll
        for (int q = 0; q < 4; q++) o[f][q] = 0.f;

    const int nkt = 2 * (qt + 1);
    for (int kt = 0; kt < nkt; kt++) {
        const int k0 = kt * 64;
        __syncthreads();   // prior PV done: Vbuf/Ps safe to overwrite

        // issue V(kt); its latency is hidden by S-mma + softmax
#pragma unroll
        for (int i = 0; i < 8; i++) {
            int idx = i * 256 + tid;
            int row = idx >> 4;          // d 0..127
            int g   = idx & 15;          // 16 granules (64 f32)
            cpasync16(sb + AV_OFF + sw16(row, g, 16),
                      g_vt + ((size_t)(kvh * HD + row)) * S_LEN + k0 + g * 4);
        }
        cpcommit();

        asm volatile("cp.async.wait_group 1;");  // K(kt) (+Q at kt=0) arrived
        __syncthreads();

        // S = Q K^T : per warp 16x64
        const uint32_t ks = sb + AK_OFF + (uint32_t)(kt & 1) * 32768;
        float s[8][4];
#pragma unroll
        for (int f = 0; f < 8; f++)
#pragma unroll
            for (int q = 0; q < 4; q++) s[f][q] = 0.f;

#pragma unroll 4
        for (int kk = 0; kk < 16; kk++) {
            uint32_t a[4];
            ldm4s(a, sb + AQ_OFF, 16 * w, kk * 8, 32);
#pragma unroll
            for (int j = 0; j < 4; j++) {
                uint32_t b[4];
                ldm4s(b, ks, 16 * j, kk * 8, 32);
                mma8(s[2 * j],     a, b[0], b[2]);
                mma8(s[2 * j + 1], a, b[1], b[3]);
            }
        }

        // mask + scale
        const int r0g = q0 + 16 * w + (lane >> 2);
        const int r1g = r0g + 8;
#pragma unroll
        for (int f = 0; f < 8; f++) {
            int c0g = k0 + 8 * f + 2 * (lane & 3);
            s[f][0] = (c0g     <= r0g) ? s[f][0] * scale : -CUDART_INF_F;
            s[f][1] = (c0g + 1 <= r0g) ? s[f][1] * scale : -CUDART_INF_F;
            s[f][2] = (c0g     <= r1g) ? s[f][2] * scale : -CUDART_INF_F;
            s[f][3] = (c0g + 1 <= r1g) ? s[f][3] * scale : -CUDART_INF_F;
        }

        // online softmax
        float mx0 = -CUDART_INF_F, mx1 = -CUDART_INF_F;
#pragma unroll
        for (int f = 0; f < 8; f++) {
            mx0 = fmaxf(mx0, fmaxf(s[f][0], s[f][1]));
            mx1 = fmaxf(mx1, fmaxf(s[f][2], s[f][3]));
        }
        mx0 = fmaxf(mx0, __shfl_xor_sync(0xffffffffu, mx0, 1));
        mx0 = fmaxf(mx0, __shfl_xor_sync(0xffffffffu, mx0, 2));
        mx1 = fmaxf(mx1, __shfl_xor_sync(0xffffffffu, mx1, 1));
        mx1 = fmaxf(mx1, __shfl_xor_sync(0xffffffffu, mx1, 2));

        float mn0 = fmaxf(m0, mx0), mn1 = fmaxf(m1, mx1);
        float al0 = __expf(m0 - mn0), al1 = __expf(m1 - mn1);
        m0 = mn0; m1 = mn1;

        float rs0 = 0.f, rs1 = 0.f;
#pragma unroll
        for (int f = 0; f < 8; f++) {
            s[f][0] = __expf(s[f][0] - m0);
            s[f][1] = __expf(s[f][1] - m0);
            s[f][2] = __expf(s[f][2] - m1);
            s[f][3] = __expf(s[f][3] - m1);
            rs0 += s[f][0] + s[f][1];
            rs1 += s[f][2] + s[f][3];
        }
        rs0 += __shfl_xor_sync(0xffffffffu, rs0, 1);
        rs0 += __shfl_xor_sync(0xffffffffu, rs0, 2);
        rs1 += __shfl_xor_sync(0xffffffffu, rs1, 1);
        rs1 += __shfl_xor_sync(0xffffffffu, rs1, 2);
        l0 = l0 * al0 + rs0;
        l1 = l1 * al1 + rs1;

#pragma unroll
        for (int f = 0; f < 16; f++) {
            o[f][0] *= al0; o[f][1] *= al0;
            o[f][2] *= al1; o[f][3] *= al1;
        }

        // P -> Ps (tf32-rounded), warp-private rows
        const int lr0 = 16 * w + (lane >> 2);
#pragma unroll
        for (int f = 0; f < 8; f++) {
            int cc = 8 * f + 2 * (lane & 3);
            *(float2*)(Ps + lr0 * 68 + cc) =
                make_float2(tf32r(s[f][0]), tf32r(s[f][1]));
            *(float2*)(Ps + (lr0 + 8) * 68 + cc) =
                make_float2(tf32r(s[f][2]), tf32r(s[f][3]));
        }
        __syncwarp();

        // prefetch K(kt+1), then ensure V(kt) arrived
        if (kt + 1 < nkt) {
            const int nk0 = (kt + 1) * 64;
            const uint32_t kd = sb + AK_OFF + (uint32_t)((kt + 1) & 1) * 32768;
#pragma unroll
            for (int i = 0; i < 8; i++) {
                int idx = i * 256 + tid;
                int row = idx >> 5;
                int g   = idx & 31;
                cpasync16(kd + sw16(row, g, 32),
                          g_qkv + (size_t)(nk0 + row) * FQKV + NH * HD + kvh * HD + g * 4);
            }
            cpcommit();
            asm volatile("cp.async.wait_group 1;");   // V(kt) done
        } else {
            asm volatile("cp.async.wait_group 0;");
        }
        __syncthreads();

        // O += P V : per warp 16x128
#pragma unroll 2
        for (int kk = 0; kk < 8; kk++) {
            uint32_t a[4];
            ldm4(a, Ps, 16 * w, kk * 8, 68);
#pragma unroll
            for (int j = 0; j < 8; j++) {
                uint32_t b[4];
                ldm4s(b, sb + AV_OFF, 16 * j, kk * 8, 16);
                mma8(o[2 * j],     a, b[0], b[2]);
                mma8(o[2 * j + 1], a, b[1], b[3]);
            }
        }
    }

    // epilogue: normalize + tf32-round (ctx feeds tf32 dense GEMM)
    const float inv0 = 1.f / l0, inv1 = 1.f / l1;
    const int gr0 = q0 + 16 * w + (lane >> 2);
    const int gr1 = gr0 + 8;
#pragma unroll
    for (int f = 0; f < 16; f++) {
        int cc = h * HD + 8 * f + 2 * (lane & 3);
        *(float2*)(g_ctx + (size_t)gr0 * EMB + cc) =
            make_float2(tf32r(o[f][0] * inv0), tf32r(o[f][1] * inv0));
        *(float2*)(g_ctx + (size_t)gr1 * EMB + cc) =
            make_float2(tf32r(o[f][2] * inv1), tf32r(o[f][3] * inv1));
    }
}

// ---------------------------------------------------------------------------
// Launch
// ---------------------------------------------------------------------------
extern "C" void kernel_launch(void* const* d_in, const int* in_sizes, int n_in,
                              void* d_out, int out_size)
{
    const float* x       = (const float*)d_in[0];
    const float* w_qkv   = (const float*)d_in[1];
    const float* w_dense = (const float*)d_in[2];
    float* out = (float*)d_out;

    float *qkv, *ctx, *xr, *wqkvr, *wdr;
    cudaGetSymbolAddress((void**)&qkv,   g_qkv);
    cudaGetSymbolAddress((void**)&ctx,   g_ctx);
    cudaGetSymbolAddress((void**)&xr,    g_xr);
    cudaGetSymbolAddress((void**)&wqkvr, g_wqkvr);
    cudaGetSymbolAddress((void**)&wdr,   g_wdr);

    cudaFuncSetAttribute(gemm_mma, cudaFuncAttributeMaxDynamicSharedMemorySize, GEMM_SMEM);
    cudaFuncSetAttribute(flash_attn_mma, cudaFuncAttributeMaxDynamicSharedMemorySize, ATT_SMEM);

    // 0) tf32-round inputs
    round_tf32_kernel<<<512, 256>>>(x,       xr,    S_LEN * EMB / 4);
    round_tf32_kernel<<<512, 256>>>(w_qkv,   wqkvr, FQKV * EMB / 4);
    round_tf32_kernel<<<512, 256>>>(w_dense, wdr,   EMB * EMB / 4);

    // 1) qkv = x @ w_qkv^T   (M=2048, N=3072, K=2048)
    gemm_mma<<<dim3(FQKV / 128, S_LEN / 128), 128, GEMM_SMEM>>>(xr, wqkvr, qkv, FQKV);
    // 2) RoPE (tf32-rounded output)
    rope_kernel<<<dim3(S_LEN, NH + NKV), 64>>>();
    // 3) V transpose + round
    vtrans_kernel<<<dim3(S_LEN / 32, HD / 32, NKV), dim3(32, 8)>>>();
    // 4) causal GQA flash attention -> ctx
    flash_attn_mma<<<dim3(NH, S_LEN / 128), 256, ATT_SMEM>>>();
    // 5) out = ctx @ w_dense^T  (M=2048, N=2048, K=2048)
    gemm_mma<<<dim3(EMB / 128, S_LEN / 128), 128, GEMM_SMEM>>>(ctx, wdr, out, EMB);
}

// round 12
// speedup vs baseline: 1.5226x; 1.5226x over previous
#include <cuda_runtime.h>
#include <cuda_fp16.h>
#include <math_constants.h>
#include <math.h>
#include <cstdint>

// Problem constants
#define S_LEN 2048
#define EMB   2048
#define NH    16
#define NKV   4
#define HD    128
#define FQKV  3072   // NH*HD + 2*NKV*HD
#define GK    2048   // K dim (elements) of BOTH projection GEMMs

// Scratch (device globals: no allocations allowed)
__device__ float  g_qkv[S_LEN * FQKV];      // 25 MB f32 (Q,K tf32-rounded by rope)
__device__ float  g_vt[NKV * HD * S_LEN];   //  4 MB (V transposed, tf32-rounded)
__device__ __half g_xh[S_LEN * EMB];        //  8 MB fp16 x
__device__ __half g_wqh[FQKV * EMB];        // 12 MB fp16 w_qkv
__device__ __half g_wdh[EMB * EMB];         //  8 MB fp16 w_dense
__device__ __half g_ctxh[S_LEN * EMB];      //  8 MB fp16 ctx

// ---------------------------------------------------------------------------
// Helpers
// ---------------------------------------------------------------------------
__device__ __forceinline__ uint32_t smem_u32(const void* p) {
    uint32_t a;
    asm("{ .reg .u64 t; cvta.to.shared.u64 t, %1; cvt.u32.u64 %0, t; }"
        : "=r"(a) : "l"(p));
    return a;
}

__device__ __forceinline__ float tf32r(float x) {
    uint32_t u;
    asm("cvt.rna.tf32.f32 %0, %1;" : "=r"(u) : "f"(x));
    return __uint_as_float(u);
}

// tf32: D += A(16x8) * B(8x8)
__device__ __forceinline__ void mma8(float* c, const uint32_t* a,
                                     uint32_t b0, uint32_t b1) {
    asm volatile(
        "mma.sync.aligned.m16n8k8.row.col.f32.tf32.tf32.f32 "
        "{%0,%1,%2,%3}, {%4,%5,%6,%7}, {%8,%9}, {%0,%1,%2,%3};\n"
        : "+f"(c[0]), "+f"(c[1]), "+f"(c[2]), "+f"(c[3])
        : "r"(a[0]), "r"(a[1]), "r"(a[2]), "r"(a[3]), "r"(b0), "r"(b1));
}

// fp16: D += A(16x16) * B(16x8), f32 accum
__device__ __forceinline__ void mma16(float* c, const uint32_t* a,
                                      uint32_t b0, uint32_t b1) {
    asm volatile(
        "mma.sync.aligned.m16n8k16.row.col.f32.f16.f16.f32 "
        "{%0,%1,%2,%3}, {%4,%5,%6,%7}, {%8,%9}, {%0,%1,%2,%3};\n"
        : "+f"(c[0]), "+f"(c[1]), "+f"(c[2]), "+f"(c[3])
        : "r"(a[0]), "r"(a[1]), "r"(a[2]), "r"(a[3]), "r"(b0), "r"(b1));
}

// byte offset of 16B granule (row, g) in an XOR-swizzled tile; gper granules/row
__device__ __forceinline__ uint32_t sw16(int row, int g, int gper) {
    return (uint32_t)(row * gper + (((g ^ row) & 7) | (g & ~7))) * 16;
}

__device__ __forceinline__ void ldm4i(uint32_t* r, uint32_t addr) {
    asm volatile("ldmatrix.sync.aligned.m8n8.x4.shared.b16 {%0,%1,%2,%3}, [%4];"
                 : "=r"(r[0]), "=r"(r[1]), "=r"(r[2]), "=r"(r[3]) : "r"(addr));
}

// tf32 ldmatrix.x4: 16 rows x 8 f32 cols from swizzled tile
__device__ __forceinline__ void ldm4s(uint32_t* r, uint32_t sbase,
                                      int row0, int col0, int gper) {
    int t = threadIdx.x & 31;
    int rr = row0 + (t & 15);
    int gc = (col0 >> 2) + (t >> 4);
    ldm4i(r, sbase + sw16(rr, gc, gper));
}

// fp16 ldmatrix.x4: 16 rows x 16 b16 cols (k-step kk of 32B) from swizzled tile
__device__ __forceinline__ void ldm4h(uint32_t* r, uint32_t sbase,
                                      int row0, int kk, int gper) {
    int t = threadIdx.x & 31;
    int rr = row0 + (t & 15);
    int gc = 2 * kk + (t >> 4);
    ldm4i(r, sbase + sw16(rr, gc, gper));
}

// tf32 ldmatrix.x4 from padded (unswizzled) f32 tile
__device__ __forceinline__ void ldm4(uint32_t* r, const float* base,
                                     int row0, int col0, int stride) {
    int t = threadIdx.x & 31;
    int rr = row0 + (t & 15);
    int cc = col0 + ((t >> 4) << 2);
    ldm4i(r, smem_u32(base + rr * stride + cc));
}

__device__ __forceinline__ void cpasync16(uint32_t dst, const void* src) {
    asm volatile("cp.async.cg.shared.global [%0], [%1], 16;" :: "r"(dst), "l"(src));
}
__device__ __forceinline__ void cpcommit() {
    asm volatile("cp.async.commit_group;");
}

// ---------------------------------------------------------------------------
// f32 -> fp16 (rn) conversion
// ---------------------------------------------------------------------------
__global__ void tohalf_kernel(const float* __restrict__ in,
                              __half* __restrict__ out, int n4) {
    int i = blockIdx.x * blockDim.x + threadIdx.x;
    for (; i < n4; i += gridDim.x * blockDim.x) {
        float4 v = ((const float4*)in)[i];
        __half2 h0 = __floats2half2_rn(v.x, v.y);
        __half2 h1 = __floats2half2_rn(v.z, v.w);
        ((__half2*)out)[2 * i]     = h0;
        ((__half2*)out)[2 * i + 1] = h1;
    }
}

// ---------------------------------------------------------------------------
// fp16 mma GEMM: C[m,n] = sum_k A[m,k]*B[n,k], A/B fp16 [.,2048], C f32.
// Block 128x128, BK=64 (128B/row), 4 warps (64x64 warp tile), 2-stage
// cp.async, XOR-swizzled smem (64KB) -> 3 CTAs/SM. R8 loop structure.
// ---------------------------------------------------------------------------
#define GEMM_SMEM 65536   // 2 stages x (A 16KB + B 16KB)

__device__ __forceinline__ void gemm_issue_h(const __half* __restrict__ A,
                                             const __half* __restrict__ B,
                                             uint32_t sb, int stage,
                                             int bm, int bn, int k0, int tid) {
    uint32_t as = sb + stage * 32768;
    uint32_t bs = as + 16384;
#pragma unroll
    for (int i = 0; i < 8; i++) {
        int idx = i * 128 + tid;      // 0..1023
        int row = idx >> 3;           // 0..127
        int g   = idx & 7;            // granule (64 fp16/row -> 8 granules)
        uint32_t off = sw16(row, g, 8);
        cpasync16(as + off, A + (size_t)(bm + row) * GK + k0 + g * 8);
        cpasync16(bs + off, B + (size_t)(bn + row) * GK + k0 + g * 8);
    }
    cpcommit();
}

__global__ __launch_bounds__(128, 3) void gemm_mma_h(const __half* __restrict__ A,
                                                     const __half* __restrict__ B,
                                                     float* __restrict__ C, int N) {
    extern __shared__ float sm[];
    const uint32_t sb = smem_u32(sm);
    const int tid = threadIdx.x;
    const int lane = tid & 31;
    const int wid = tid >> 5;          // 0..3
    const int bm = blockIdx.y * 128;
    const int bn = blockIdx.x * 128;
    const int wm = (wid >> 1) * 64;
    const int wn = (wid & 1) * 64;

    float acc[4][8][4];
#pragma unroll
    for (int i = 0; i < 4; i++)
#pragma unroll
        for (int j = 0; j < 8; j++)
#pragma unroll
            for (int q = 0; q < 4; q++) acc[i][j][q] = 0.f;

    const int NC = GK / 64;            // 32 chunks
    gemm_issue_h(A, B, sb, 0, bm, bn, 0, tid);

    for (int c = 0; c < NC; c++) {
        if (c + 1 < NC) {
            gemm_issue_h(A, B, sb, (c + 1) & 1, bm, bn, (c + 1) * 64, tid);
            asm volatile("cp.async.wait_group 1;");
        } else {
            asm volatile("cp.async.wait_group 0;");
        }
        __syncthreads();

        const uint32_t as = sb + (c & 1) * 32768;
        const uint32_t bs = as + 16384;
#pragma unroll
        for (int kk = 0; kk < 4; kk++) {      // 4 x k16
            uint32_t a[4][4];
#pragma unroll
            for (int mf = 0; mf < 4; mf++)
                ldm4h(a[mf], as, wm + 16 * mf, kk, 8);
#pragma unroll
            for (int nf = 0; nf < 4; nf++) {   // 16-wide n groups
                uint32_t b[4];
                ldm4h(b, bs, wn + 16 * nf, kk, 8);
#pragma unroll
                for (int mf = 0; mf < 4; mf++) {
                    mma16(acc[mf][2 * nf],     a[mf], b[0], b[2]);
                    mma16(acc[mf][2 * nf + 1], a[mf], b[1], b[3]);
                }
            }
        }
        __syncthreads();
    }

#pragma unroll
    for (int mf = 0; mf < 4; mf++) {
        int r0 = bm + wm + mf * 16 + (lane >> 2);
#pragma unroll
        for (int nf = 0; nf < 8; nf++) {
            int cc = bn + wn + nf * 8 + 2 * (lane & 3);
            *(float2*)(C + (size_t)r0 * N + cc) =
                make_float2(acc[mf][nf][0], acc[mf][nf][1]);
            *(float2*)(C + (size_t)(r0 + 8) * N + cc) =
                make_float2(acc[mf][nf][2], acc[mf][nf][3]);
        }
    }
}

// ---------------------------------------------------------------------------
// RoPE in-place on Q,K heads of g_qkv; output tf32-rounded
// ---------------------------------------------------------------------------
__global__ void rope_kernel() {
    int s    = blockIdx.x;
    int head = blockIdx.y;
    int i    = threadIdx.x;

    size_t off = (size_t)s * FQKV +
                 ((head < NH) ? (size_t)head * HD
                              : (size_t)NH * HD + (size_t)(head - NH) * HD);
    float* base = g_qkv + off;

    float inv_freq = expf(-(float)(2 * i) * (9.210340371976184f / 128.f));
    float ang = (float)s * inv_freq;
    float c, sn;
    sincosf(ang, &sn, &c);

    float x1 = base[i];
    float x2 = base[i + 64];
    base[i]      = tf32r(x1 * c - x2 * sn);
    base[i + 64] = tf32r(x2 * c + x1 * sn);
}

// ---------------------------------------------------------------------------
// V transpose: g_vt[kvh*HD + d][s] = tf32r(V[s][kvh][d])
// ---------------------------------------------------------------------------
__global__ void vtrans_kernel() {
    __shared__ float t[32][33];
    int kvh = blockIdx.z;
    int s0 = blockIdx.x * 32, d0 = blockIdx.y * 32;
    int tx = threadIdx.x, ty = threadIdx.y;   // 32 x 8
#pragma unroll
    for (int i = 0; i < 32; i += 8)
        t[ty + i][tx] =
            g_qkv[(size_t)(s0 + ty + i) * FQKV + (NH + NKV) * HD + kvh * HD + d0 + tx];
    __syncthreads();
#pragma unroll
    for (int i = 0; i < 32; i += 8)
        g_vt[((size_t)kvh * HD + d0 + ty + i) * S_LEN + s0 + tx] = tf32r(t[tx][ty + i]);
}

// ---------------------------------------------------------------------------
// Flash attention, mma tf32, cp.async-pipelined (R8 structure, pass-verified).
// Epilogue now writes fp16 ctx (feeds fp16 dense GEMM).
// ---------------------------------------------------------------------------
#define AQ_OFF 0
#define AK_OFF 65536
#define AV_OFF 131072
#define AP_F32 40960                 // Ps f32 index base (byte 163840)
#define ATT_SMEM 198656

__global__ __launch_bounds__(256, 1) void flash_attn_mma() {
    extern __shared__ float sm[];
    const uint32_t sb = smem_u32(sm);
    float* Ps = sm + AP_F32;

    const int tid = threadIdx.x;
    const int lane = tid & 31;
    const int w = tid >> 5;
    const int h = blockIdx.x;
    const int kvh = h >> 2;
    const int qt = (int)gridDim.y - 1 - (int)blockIdx.y;  // heavy first
    const int q0 = qt * 128;
    const float scale = 0.08838834764831845f;   // 1/sqrt(128)

    // prologue: Q + K(0) as one commit group
    {
#pragma unroll
        for (int i = 0; i < 16; i++) {
            int idx = i * 256 + tid;
            int row = idx >> 5;
            int g   = idx & 31;
            cpasync16(sb + AQ_OFF + sw16(row, g, 32),
                      g_qkv + (size_t)(q0 + row) * FQKV + h * HD + g * 4);
        }
#pragma unroll
        for (int i = 0; i < 8; i++) {
            int idx = i * 256 + tid;
            int row = idx >> 5;
            int g   = idx & 31;
            cpasync16(sb + AK_OFF + sw16(row, g, 32),
                      g_qkv + (size_t)(row) * FQKV + NH * HD + kvh * HD + g * 4);
        }
        cpcommit();
    }

    float m0 = -CUDART_INF_F, m1 = -CUDART_INF_F, l0 = 0.f, l1 = 0.f;
    float o[16][4];
#pragma unroll
    for (int f = 0; f < 16; f++)
#pragma unroll
        for (int q = 0; q < 4; q++) o[f][q] = 0.f;

    const int nkt = 2 * (qt + 1);
    for (int kt = 0; kt < nkt; kt++) {
        const int k0 = kt * 64;
        __syncthreads();   // prior PV done: Vbuf/Ps safe to overwrite

        // issue V(kt); latency hidden by S-mma + softmax
#pragma unroll
        for (int i = 0; i < 8; i++) {
            int idx = i * 256 + tid;
            int row = idx >> 4;          // d 0..127
            int g   = idx & 15;          // 16 granules (64 f32)
            cpasync16(sb + AV_OFF + sw16(row, g, 16),
                      g_vt + ((size_t)(kvh * HD + row)) * S_LEN + k0 + g * 4);
        }
        cpcommit();

        asm volatile("cp.async.wait_group 1;");  // K(kt) (+Q at kt=0) arrived
        __syncthreads();

        // S = Q K^T : per warp 16x64
        const uint32_t ks = sb + AK_OFF + (uint32_t)(kt & 1) * 32768;
        float s[8][4];
#pragma unroll
        for (int f = 0; f < 8; f++)
#pragma unroll
            for (int q = 0; q < 4; q++) s[f][q] = 0.f;

#pragma unroll 4
        for (int kk = 0; kk < 16; kk++) {
            uint32_t a[4];
            ldm4s(a, sb + AQ_OFF, 16 * w, kk * 8, 32);
#pragma unroll
            for (int j = 0; j < 4; j++) {
                uint32_t b[4];
                ldm4s(b, ks, 16 * j, kk * 8, 32);
                mma8(s[2 * j],     a, b[0], b[2]);
                mma8(s[2 * j + 1], a, b[1], b[3]);
            }
        }

        // mask + scale
        const int r0g = q0 + 16 * w + (lane >> 2);
        const int r1g = r0g + 8;
#pragma unroll
        for (int f = 0; f < 8; f++) {
            int c0g = k0 + 8 * f + 2 * (lane & 3);
            s[f][0] = (c0g     <= r0g) ? s[f][0] * scale : -CUDART_INF_F;
            s[f][1] = (c0g + 1 <= r0g) ? s[f][1] * scale : -CUDART_INF_F;
            s[f][2] = (c0g     <= r1g) ? s[f][2] * scale : -CUDART_INF_F;
            s[f][3] = (c0g + 1 <= r1g) ? s[f][3] * scale : -CUDART_INF_F;
        }

        // online softmax
        float mx0 = -CUDART_INF_F, mx1 = -CUDART_INF_F;
#pragma unroll
        for (int f = 0; f < 8; f++) {
            mx0 = fmaxf(mx0, fmaxf(s[f][0], s[f][1]));
            mx1 = fmaxf(mx1, fmaxf(s[f][2], s[f][3]));
        }
        mx0 = fmaxf(mx0, __shfl_xor_sync(0xffffffffu, mx0, 1));
        mx0 = fmaxf(mx0, __shfl_xor_sync(0xffffffffu, mx0, 2));
        mx1 = fmaxf(mx1, __shfl_xor_sync(0xffffffffu, mx1, 1));
        mx1 = fmaxf(mx1, __shfl_xor_sync(0xffffffffu, mx1, 2));

        float mn0 = fmaxf(m0, mx0), mn1 = fmaxf(m1, mx1);
        float al0 = __expf(m0 - mn0), al1 = __expf(m1 - mn1);
        m0 = mn0; m1 = mn1;

        float rs0 = 0.f, rs1 = 0.f;
#pragma unroll
        for (int f = 0; f < 8; f++) {
            s[f][0] = __expf(s[f][0] - m0);
            s[f][1] = __expf(s[f][1] - m0);
            s[f][2] = __expf(s[f][2] - m1);
            s[f][3] = __expf(s[f][3] - m1);
            rs0 += s[f][0] + s[f][1];
            rs1 += s[f][2] + s[f][3];
        }
        rs0 += __shfl_xor_sync(0xffffffffu, rs0, 1);
        rs0 += __shfl_xor_sync(0xffffffffu, rs0, 2);
        rs1 += __shfl_xor_sync(0xffffffffu, rs1, 1);
        rs1 += __shfl_xor_sync(0xffffffffu, rs1, 2);
        l0 = l0 * al0 + rs0;
        l1 = l1 * al1 + rs1;

#pragma unroll
        for (int f = 0; f < 16; f++) {
            o[f][0] *= al0; o[f][1] *= al0;
            o[f][2] *= al1; o[f][3] *= al1;
        }

        // P -> Ps (tf32-rounded), warp-private rows
        const int lr0 = 16 * w + (lane >> 2);
#pragma unroll
        for (int f = 0; f < 8; f++) {
            int cc = 8 * f + 2 * (lane & 3);
            *(float2*)(Ps + lr0 * 68 + cc) =
                make_float2(tf32r(s[f][0]), tf32r(s[f][1]));
            *(float2*)(Ps + (lr0 + 8) * 68 + cc) =
                make_float2(tf32r(s[f][2]), tf32r(s[f][3]));
        }
        __syncwarp();

        // prefetch K(kt+1), then ensure V(kt) arrived
        if (kt + 1 < nkt) {
            const int nk0 = (kt + 1) * 64;
            const uint32_t kd = sb + AK_OFF + (uint32_t)((kt + 1) & 1) * 32768;
#pragma unroll
            for (int i = 0; i < 8; i++) {
                int idx = i * 256 + tid;
                int row = idx >> 5;
                int g   = idx & 31;
                cpasync16(kd + sw16(row, g, 32),
                          g_qkv + (size_t)(nk0 + row) * FQKV + NH * HD + kvh * HD + g * 4);
            }
            cpcommit();
            asm volatile("cp.async.wait_group 1;");   // V(kt) done
        } else {
            asm volatile("cp.async.wait_group 0;");
        }
        __syncthreads();

        // O += P V : per warp 16x128
#pragma unroll 2
        for (int kk = 0; kk < 8; kk++) {
            uint32_t a[4];
            ldm4(a, Ps, 16 * w, kk * 8, 68);
#pragma unroll
            for (int j = 0; j < 8; j++) {
                uint32_t b[4];
                ldm4s(b, sb + AV_OFF, 16 * j, kk * 8, 16);
                mma8(o[2 * j],     a, b[0], b[2]);
                mma8(o[2 * j + 1], a, b[1], b[3]);
            }
        }
    }

    // epilogue: normalize, write fp16 ctx
    const float inv0 = 1.f / l0, inv1 = 1.f / l1;
    const int gr0 = q0 + 16 * w + (lane >> 2);
    const int gr1 = gr0 + 8;
#pragma unroll
    for (int f = 0; f < 16; f++) {
        int cc = h * HD + 8 * f + 2 * (lane & 3);
        *(__half2*)(g_ctxh + (size_t)gr0 * EMB + cc) =
            __floats2half2_rn(o[f][0] * inv0, o[f][1] * inv0);
        *(__half2*)(g_ctxh + (size_t)gr1 * EMB + cc) =
            __floats2half2_rn(o[f][2] * inv1, o[f][3] * inv1);
    }
}

// ---------------------------------------------------------------------------
// Launch
// ---------------------------------------------------------------------------
extern "C" void kernel_launch(void* const* d_in, const int* in_sizes, int n_in,
                              void* d_out, int out_size)
{
    const float* x       = (const float*)d_in[0];
    const float* w_qkv   = (const float*)d_in[1];
    const float* w_dense = (const float*)d_in[2];
    float* out = (float*)d_out;

    float *qkv;
    __half *xh, *wqh, *wdh, *ctxh;
    cudaGetSymbolAddress((void**)&qkv,  g_qkv);
    cudaGetSymbolAddress((void**)&xh,   g_xh);
    cudaGetSymbolAddress((void**)&wqh,  g_wqh);
    cudaGetSymbolAddress((void**)&wdh,  g_wdh);
    cudaGetSymbolAddress((void**)&ctxh, g_ctxh);

    cudaFuncSetAttribute(gemm_mma_h, cudaFuncAttributeMaxDynamicSharedMemorySize, GEMM_SMEM);
    cudaFuncSetAttribute(flash_attn_mma, cudaFuncAttributeMaxDynamicSharedMemorySize, ATT_SMEM);

    // 0) fp16 conversions
    tohalf_kernel<<<512, 256>>>(x,       xh,  S_LEN * EMB / 4);
    tohalf_kernel<<<512, 256>>>(w_qkv,   wqh, FQKV * EMB / 4);
    tohalf_kernel<<<512, 256>>>(w_dense, wdh, EMB * EMB / 4);

    // 1) qkv = x @ w_qkv^T   (fp16 mma, f32 out)
    gemm_mma_h<<<dim3(FQKV / 128, S_LEN / 128), 128, GEMM_SMEM>>>(xh, wqh, qkv, FQKV);
    // 2) RoPE (tf32-rounded output)
    rope_kernel<<<dim3(S_LEN, NH + NKV), 64>>>();
    // 3) V transpose + round
    vtrans_kernel<<<dim3(S_LEN / 32, HD / 32, NKV), dim3(32, 8)>>>();
    // 4) causal GQA flash attention -> fp16 ctx
    flash_attn_mma<<<dim3(NH, S_LEN / 128), 256, ATT_SMEM>>>();
    // 5) out = ctx @ w_dense^T  (fp16 mma, f32 out)
    gemm_mma_h<<<dim3(EMB / 128, S_LEN / 128), 128, GEMM_SMEM>>>(ctxh, wdh, out, EMB);
}

// round 15
// speedup vs baseline: 1.8190x; 1.1947x over previous
#include <cuda_runtime.h>
#include <cuda_fp16.h>
#include <math_constants.h>
#include <math.h>
#include <cstdint>

// Problem constants
#define S_LEN 2048
#define EMB   2048
#define NH    16
#define NKV   4
#define HD    128
#define FQKV  3072   // NH*HD + 2*NKV*HD
#define GK    2048   // K dim (elements) of BOTH projection GEMMs

// Scratch (device globals: no allocations allowed)
__device__ float  g_qkv[S_LEN * FQKV];        // 25 MB f32 qkv (pre-rope)
__device__ __half g_xh[S_LEN * EMB];          //  8 MB fp16 x
__device__ __half g_wqh[FQKV * EMB];          // 12 MB fp16 w_qkv
__device__ __half g_wdh[EMB * EMB];           //  8 MB fp16 w_dense
__device__ __half g_ctxh[S_LEN * EMB];        //  8 MB fp16 ctx
__device__ __half g_qh[S_LEN * NH * HD];      //  8 MB fp16 roped Q
__device__ __half g_kh[S_LEN * NKV * HD];     //  2 MB fp16 roped K
__device__ __half g_vth[NKV * HD * S_LEN];    //  2 MB fp16 V transposed

// ---------------------------------------------------------------------------
// Helpers
// ---------------------------------------------------------------------------
__device__ __forceinline__ uint32_t smem_u32(const void* p) {
    uint32_t a;
    asm("{ .reg .u64 t; cvta.to.shared.u64 t, %1; cvt.u32.u64 %0, t; }"
        : "=r"(a) : "l"(p));
    return a;
}

// fp16: D += A(16x16) * B(16x8), f32 accum
__device__ __forceinline__ void mma16(float* c, const uint32_t* a,
                                      uint32_t b0, uint32_t b1) {
    asm volatile(
        "mma.sync.aligned.m16n8k16.row.col.f32.f16.f16.f32 "
        "{%0,%1,%2,%3}, {%4,%5,%6,%7}, {%8,%9}, {%0,%1,%2,%3};\n"
        : "+f"(c[0]), "+f"(c[1]), "+f"(c[2]), "+f"(c[3])
        : "r"(a[0]), "r"(a[1]), "r"(a[2]), "r"(a[3]), "r"(b0), "r"(b1));
}

// byte offset of 16B granule (row, g) in an XOR-swizzled tile; gper granules/row
__device__ __forceinline__ uint32_t sw16(int row, int g, int gper) {
    return (uint32_t)(row * gper + (((g ^ row) & 7) | (g & ~7))) * 16;
}

__device__ __forceinline__ void ldm4i(uint32_t* r, uint32_t addr) {
    asm volatile("ldmatrix.sync.aligned.m8n8.x4.shared.b16 {%0,%1,%2,%3}, [%4];"
                 : "=r"(r[0]), "=r"(r[1]), "=r"(r[2]), "=r"(r[3]) : "r"(addr));
}

// fp16 ldmatrix.x4: 16 rows x 16 fp16 cols (k-step kk of 32B) from swizzled tile
__device__ __forceinline__ void ldm4h(uint32_t* r, uint32_t sbase,
                                      int row0, int kk, int gper) {
    int t = threadIdx.x & 31;
    int rr = row0 + (t & 15);
    int gc = 2 * kk + (t >> 4);
    ldm4i(r, sbase + sw16(rr, gc, gper));
}

// fp16 ldmatrix.x4 from padded (unswizzled) fp16 tile, stride in fp16 elems
__device__ __forceinline__ void ldm4hp(uint32_t* r, const __half* base,
                                       int row0, int kk, int stride) {
    int t = threadIdx.x & 31;
    int rr = row0 + (t & 15);
    int cc = kk * 16 + ((t >> 4) << 3);
    ldm4i(r, smem_u32(base + rr * stride + cc));
}

__device__ __forceinline__ void cpasync16(uint32_t dst, const void* src) {
    asm volatile("cp.async.cg.shared.global [%0], [%1], 16;" :: "r"(dst), "l"(src));
}
__device__ __forceinline__ void cpcommit() {
    asm volatile("cp.async.commit_group;");
}

// ---------------------------------------------------------------------------
// f32 -> fp16 (rn) conversion
// ---------------------------------------------------------------------------
__global__ void tohalf_kernel(const float* __restrict__ in,
                              __half* __restrict__ out, int n4) {
    int i = blockIdx.x * blockDim.x + threadIdx.x;
    for (; i < n4; i += gridDim.x * blockDim.x) {
        float4 v = ((const float4*)in)[i];
        ((__half2*)out)[2 * i]     = __floats2half2_rn(v.x, v.y);
        ((__half2*)out)[2 * i + 1] = __floats2half2_rn(v.z, v.w);
    }
}

// ---------------------------------------------------------------------------
// fp16 mma GEMM (unchanged from R12 pass): C[m,n] = sum_k A[m,k]*B[n,k].
// Block 128x128, BK=64, 4 warps (64x64), 2-stage cp.async, swizzled smem.
// ---------------------------------------------------------------------------
#define GEMM_SMEM 65536

__device__ __forceinline__ void gemm_issue_h(const __half* __restrict__ A,
                                             const __half* __restrict__ B,
                                             uint32_t sb, int stage,
                                             int bm, int bn, int k0, int tid) {
    uint32_t as = sb + stage * 32768;
    uint32_t bs = as + 16384;
#pragma unroll
    for (int i = 0; i < 8; i++) {
        int idx = i * 128 + tid;
        int row = idx >> 3;
        int g   = idx & 7;
        uint32_t off = sw16(row, g, 8);
        cpasync16(as + off, A + (size_t)(bm + row) * GK + k0 + g * 8);
        cpasync16(bs + off, B + (size_t)(bn + row) * GK + k0 + g * 8);
    }
    cpcommit();
}

__global__ __launch_bounds__(128, 3) void gemm_mma_h(const __half* __restrict__ A,
                                                     const __half* __restrict__ B,
                                                     float* __restrict__ C, int N) {
    extern __shared__ float sm[];
    const uint32_t sb = smem_u32(sm);
    const int tid = threadIdx.x;
    const int lane = tid & 31;
    const int wid = tid >> 5;
    const int bm = blockIdx.y * 128;
    const int bn = blockIdx.x * 128;
    const int wm = (wid >> 1) * 64;
    const int wn = (wid & 1) * 64;

    float acc[4][8][4];
#pragma unroll
    for (int i = 0; i < 4; i++)
#pragma unroll
        for (int j = 0; j < 8; j++)
#pragma unroll
            for (int q = 0; q < 4; q++) acc[i][j][q] = 0.f;

    const int NC = GK / 64;
    gemm_issue_h(A, B, sb, 0, bm, bn, 0, tid);

    for (int c = 0; c < NC; c++) {
        if (c + 1 < NC) {
            gemm_issue_h(A, B, sb, (c + 1) & 1, bm, bn, (c + 1) * 64, tid);
            asm volatile("cp.async.wait_group 1;");
        } else {
            asm volatile("cp.async.wait_group 0;");
        }
        __syncthreads();

        const uint32_t as = sb + (c & 1) * 32768;
        const uint32_t bs = as + 16384;
#pragma unroll
        for (int kk = 0; kk < 4; kk++) {
            uint32_t a[4][4];
#pragma unroll
            for (int mf = 0; mf < 4; mf++)
                ldm4h(a[mf], as, wm + 16 * mf, kk, 8);
#pragma unroll
            for (int nf = 0; nf < 4; nf++) {
                uint32_t b[4];
                ldm4h(b, bs, wn + 16 * nf, kk, 8);
#pragma unroll
                for (int mf = 0; mf < 4; mf++) {
                    mma16(acc[mf][2 * nf],     a[mf], b[0], b[2]);
                    mma16(acc[mf][2 * nf + 1], a[mf], b[1], b[3]);
                }
            }
        }
        __syncthreads();
    }

#pragma unroll
    for (int mf = 0; mf < 4; mf++) {
        int r0 = bm + wm + mf * 16 + (lane >> 2);
#pragma unroll
        for (int nf = 0; nf < 8; nf++) {
            int cc = bn + wn + nf * 8 + 2 * (lane & 3);
            *(float2*)(C + (size_t)r0 * N + cc) =
                make_float2(acc[mf][nf][0], acc[mf][nf][1]);
            *(float2*)(C + (size_t)(r0 + 8) * N + cc) =
                make_float2(acc[mf][nf][2], acc[mf][nf][3]);
        }
    }
}

// ---------------------------------------------------------------------------
// RoPE: read f32 qkv, write fp16 Q -> g_qh[s][h][d], K -> g_kh[s][kvh][d]
// ---------------------------------------------------------------------------
__global__ void rope_kernel() {
    int s    = blockIdx.x;
    int head = blockIdx.y;          // 0..19
    int i    = threadIdx.x;         // 0..63

    size_t off = (size_t)s * FQKV +
                 ((head < NH) ? (size_t)head * HD
                              : (size_t)NH * HD + (size_t)(head - NH) * HD);
    const float* base = g_qkv + off;

    float inv_freq = expf(-(float)(2 * i) * (9.210340371976184f / 128.f));
    float ang = (float)s * inv_freq;
    float c, sn;
    sincosf(ang, &sn, &c);

    float x1 = base[i];
    float x2 = base[i + 64];
    float r1 = x1 * c - x2 * sn;
    float r2 = x2 * c + x1 * sn;

    if (head < NH) {
        __half* dst = g_qh + ((size_t)s * NH + head) * HD;
        dst[i]      = __float2half_rn(r1);
        dst[i + 64] = __float2half_rn(r2);
    } else {
        __half* dst = g_kh + ((size_t)s * NKV + (head - NH)) * HD;
        dst[i]      = __float2half_rn(r1);
        dst[i + 64] = __float2half_rn(r2);
    }
}

// ---------------------------------------------------------------------------
// V transpose: g_vth[kvh*HD + d][s] = fp16(V[s][kvh][d])
// ---------------------------------------------------------------------------
__global__ void vtrans_kernel() {
    __shared__ float t[32][33];
    int kvh = blockIdx.z;
    int s0 = blockIdx.x * 32, d0 = blockIdx.y * 32;
    int tx = threadIdx.x, ty = threadIdx.y;   // 32 x 8
#pragma unroll
    for (int i = 0; i < 32; i += 8)
        t[ty + i][tx] =
            g_qkv[(size_t)(s0 + ty + i) * FQKV + (NH + NKV) * HD + kvh * HD + d0 + tx];
    __syncthreads();
#pragma unroll
    for (int i = 0; i < 32; i += 8)
        g_vth[((size_t)kvh * HD + d0 + ty + i) * S_LEN + s0 + tx] =
            __float2half_rn(t[tx][ty + i]);
}

// ---------------------------------------------------------------------------
// Flash attention, full fp16 mma, cp.async-pipelined (R8/R12 structure).
// CTA: 128 q-rows x 1 head, 8 warps, k-tile 64.
// smem (fp16): Qs 128x256B sw (32K), Ks 2x64x256B sw (32K),
//              Vt 128x128B sw (16K), Ps fp16[128][72] (18K) = 100352 B.
// ---------------------------------------------------------------------------
#define AQ_OFF 0
#define AK_OFF 32768
#define AV_OFF 65536
#define AP_OFF 81920
#define ATT_SMEM 100352
#define PS_STRIDE 72

__global__ __launch_bounds__(256, 1) void flash_attn_mma() {
    extern __shared__ char smc[];
    const uint32_t sb = smem_u32(smc);
    __half* PsH = (__half*)(smc + AP_OFF);

    const int tid = threadIdx.x;
    const int lane = tid & 31;
    const int w = tid >> 5;
    const int h = blockIdx.x;
    const int kvh = h >> 2;
    const int qt = (int)gridDim.y - 1 - (int)blockIdx.y;  // heavy first
    const int q0 = qt * 128;
    const float scale = 0.08838834764831845f;   // 1/sqrt(128)

    // prologue: Q + K(0) as one commit group
    {
#pragma unroll
        for (int i = 0; i < 8; i++) {              // Q: 128 rows x 16 granules
            int idx = i * 256 + tid;
            int row = idx >> 4;
            int g   = idx & 15;
            cpasync16(sb + AQ_OFF + sw16(row, g, 16),
                      g_qh + ((size_t)(q0 + row) * NH + h) * HD + g * 8);
        }
#pragma unroll
        for (int i = 0; i < 4; i++) {              // K: 64 rows x 16 granules
            int idx = i * 256 + tid;
            int row = idx >> 4;
            int g   = idx & 15;
            cpasync16(sb + AK_OFF + sw16(row, g, 16),
                      g_kh + ((size_t)row * NKV + kvh) * HD + g * 8);
        }
        cpcommit();
    }

    float m0 = -CUDART_INF_F, m1 = -CUDART_INF_F, l0 = 0.f, l1 = 0.f;
    float o[16][4];
#pragma unroll
    for (int f = 0; f < 16; f++)
#pragma unroll
        for (int q = 0; q < 4; q++) o[f][q] = 0.f;

    const int nkt = 2 * (qt + 1);
    for (int kt = 0; kt < nkt; kt++) {
        const int k0 = kt * 64;
        __syncthreads();   // prior PV done: Vbuf/Ps safe to overwrite

        // issue V(kt): 128 rows (d) x 8 granules (64 fp16 s-values)
#pragma unroll
        for (int i = 0; i < 4; i++) {
            int idx = i * 256 + tid;
            int row = idx >> 3;
            int g   = idx & 7;
            cpasync16(sb + AV_OFF + sw16(row, g, 8),
                      g_vth + ((size_t)(kvh * HD + row)) * S_LEN + k0 + g * 8);
        }
        cpcommit();

        asm volatile("cp.async.wait_group 1;");  // K(kt) (+Q at kt=0) arrived
        __syncthreads();

        // S = Q K^T : per warp 16x64, 8 k16 steps
        const uint32_t ks = sb + AK_OFF + (uint32_t)(kt & 1) * 16384;
        float s[8][4];
#pragma unroll
        for (int f = 0; f < 8; f++)
#pragma unroll
            for (int q = 0; q < 4; q++) s[f][q] = 0.f;

#pragma unroll 4
        for (int kk = 0; kk < 8; kk++) {
            uint32_t a[4];
            ldm4h(a, sb + AQ_OFF, 16 * w, kk, 16);
#pragma unroll
            for (int j = 0; j < 4; j++) {
                uint32_t b[4];
                ldm4h(b, ks, 16 * j, kk, 16);
                mma16(s[2 * j],     a, b[0], b[2]);
                mma16(s[2 * j + 1], a, b[1], b[3]);
            }
        }

        // mask + scale
        const int r0g = q0 + 16 * w + (lane >> 2);
        const int r1g = r0g + 8;
#pragma unroll
        for (int f = 0; f < 8; f++) {
            int c0g = k0 + 8 * f + 2 * (lane & 3);
            s[f][0] = (c0g     <= r0g) ? s[f][0] * scale : -CUDART_INF_F;
            s[f][1] = (c0g + 1 <= r0g) ? s[f][1] * scale : -CUDART_INF_F;
            s[f][2] = (c0g     <= r1g) ? s[f][2] * scale : -CUDART_INF_F;
            s[f][3] = (c0g + 1 <= r1g) ? s[f][3] * scale : -CUDART_INF_F;
        }

        // online softmax
        float mx0 = -CUDART_INF_F, mx1 = -CUDART_INF_F;
#pragma unroll
        for (int f = 0; f < 8; f++) {
            mx0 = fmaxf(mx0, fmaxf(s[f][0], s[f][1]));
            mx1 = fmaxf(mx1, fmaxf(s[f][2], s[f][3]));
        }
        mx0 = fmaxf(mx0, __shfl_xor_sync(0xffffffffu, mx0, 1));
        mx0 = fmaxf(mx0, __shfl_xor_sync(0xffffffffu, mx0, 2));
        mx1 = fmaxf(mx1, __shfl_xor_sync(0xffffffffu, mx1, 1));
        mx1 = fmaxf(mx1, __shfl_xor_sync(0xffffffffu, mx1, 2));

        float mn0 = fmaxf(m0, mx0), mn1 = fmaxf(m1, mx1);
        float al0 = __expf(m0 - mn0), al1 = __expf(m1 - mn1);
        m0 = mn0; m1 = mn1;

        float rs0 = 0.f, rs1 = 0.f;
#pragma unroll
        for (int f = 0; f < 8; f++) {
            s[f][0] = __expf(s[f][0] - m0);
            s[f][1] = __expf(s[f][1] - m0);
            s[f][2] = __expf(s[f][2] - m1);
            s[f][3] = __expf(s[f][3] - m1);
            rs0 += s[f][0] + s[f][1];
            rs1 += s[f][2] + s[f][3];
        }
        rs0 += __shfl_xor_sync(0xffffffffu, rs0, 1);
        rs0 += __shfl_xor_sync(0xffffffffu, rs0, 2);
        rs1 += __shfl_xor_sync(0xffffffffu, rs1, 1);
        rs1 += __shfl_xor_sync(0xffffffffu, rs1, 2);
        l0 = l0 * al0 + rs0;
        l1 = l1 * al1 + rs1;

#pragma unroll
        for (int f = 0; f < 16; f++) {
            o[f][0] *= al0; o[f][1] *= al0;
            o[f][2] *= al1; o[f][3] *= al1;
        }

        // P -> Ps fp16, warp-private rows
        const int lr0 = 16 * w + (lane >> 2);
#pragma unroll
        for (int f = 0; f < 8; f++) {
            int cc = 8 * f + 2 * (lane & 3);
            *(__half2*)(PsH + lr0 * PS_STRIDE + cc) =
                __floats2half2_rn(s[f][0], s[f][1]);
            *(__half2*)(PsH + (lr0 + 8) * PS_STRIDE + cc) =
                __floats2half2_rn(s[f][2], s[f][3]);
        }
        __syncwarp();

        // prefetch K(kt+1), then ensure V(kt) arrived
        if (kt + 1 < nkt) {
            const int nk0 = (kt + 1) * 64;
            const uint32_t kd = sb + AK_OFF + (uint32_t)((kt + 1) & 1) * 16384;
#pragma unroll
            for (int i = 0; i < 4; i++) {
                int idx = i * 256 + tid;
                int row = idx >> 4;
                int g   = idx & 15;
                cpasync16(kd + sw16(row, g, 16),
                          g_kh + ((size_t)(nk0 + row) * NKV + kvh) * HD + g * 8);
            }
            cpcommit();
            asm volatile("cp.async.wait_group 1;");   // V(kt) done
        } else {
            asm volatile("cp.async.wait_group 0;");
        }
        __syncthreads();

        // O += P V : per warp 16x128, 4 k16 steps
#pragma unroll 2
        for (int kk = 0; kk < 4; kk++) {
            uint32_t a[4];
            ldm4hp(a, PsH, 16 * w, kk, PS_STRIDE);
#pragma unroll
            for (int j = 0; j < 8; j++) {
                uint32_t b[4];
                ldm4h(b, sb + AV_OFF, 16 * j, kk, 8);
                mma16(o[2 * j],     a, b[0], b[2]);
                mma16(o[2 * j + 1], a, b[1], b[3]);
            }
        }
    }

    // epilogue: normalize, write fp16 ctx
    const float inv0 = 1.f / l0, inv1 = 1.f / l1;
    const int gr0 = q0 + 16 * w + (lane >> 2);
    const int gr1 = gr0 + 8;
#pragma unroll
    for (int f = 0; f < 16; f++) {
        int cc = h * HD + 8 * f + 2 * (lane & 3);
        *(__half2*)(g_ctxh + (size_t)gr0 * EMB + cc) =
            __floats2half2_rn(o[f][0] * inv0, o[f][1] * inv0);
        *(__half2*)(g_ctxh + (size_t)gr1 * EMB + cc) =
            __floats2half2_rn(o[f][2] * inv1, o[f][3] * inv1);
    }
}

// ---------------------------------------------------------------------------
// Launch
// ---------------------------------------------------------------------------
extern "C" void kernel_launch(void* const* d_in, const int* in_sizes, int n_in,
                              void* d_out, int out_size)
{
    const float* x       = (const float*)d_in[0];
    const float* w_qkv   = (const float*)d_in[1];
    const float* w_dense = (const float*)d_in[2];
    float* out = (float*)d_out;

    float *qkv;
    __half *xh, *wqh, *wdh, *ctxh;
    cudaGetSymbolAddress((void**)&qkv,  g_qkv);
    cudaGetSymbolAddress((void**)&xh,   g_xh);
    cudaGetSymbolAddress((void**)&wqh,  g_wqh);
    cudaGetSymbolAddress((void**)&wdh,  g_wdh);
    cudaGetSymbolAddress((void**)&ctxh, g_ctxh);

    cudaFuncSetAttribute(gemm_mma_h, cudaFuncAttributeMaxDynamicSharedMemorySize, GEMM_SMEM);
    cudaFuncSetAttribute(flash_attn_mma, cudaFuncAttributeMaxDynamicSharedMemorySize, ATT_SMEM);

    // 0) fp16 conversions
    tohalf_kernel<<<512, 256>>>(x,       xh,  S_LEN * EMB / 4);
    tohalf_kernel<<<512, 256>>>(w_qkv,   wqh, FQKV * EMB / 4);
    tohalf_kernel<<<512, 256>>>(w_dense, wdh, EMB * EMB / 4);

    // 1) qkv = x @ w_qkv^T   (fp16 mma, f32 out)
    gemm_mma_h<<<dim3(FQKV / 128, S_LEN / 128), 128, GEMM_SMEM>>>(xh, wqh, qkv, FQKV);
    // 2) RoPE -> fp16 Q/K
    rope_kernel<<<dim3(S_LEN, NH + NKV), 64>>>();
    // 3) V transpose -> fp16
    vtrans_kernel<<<dim3(S_LEN / 32, HD / 32, NKV), dim3(32, 8)>>>();
    // 4) causal GQA flash attention (full fp16 mma) -> fp16 ctx
    flash_attn_mma<<<dim3(NH, S_LEN / 128), 256, ATT_SMEM>>>();
    // 5) out = ctx @ w_dense^T  (fp16 mma, f32 out)
    gemm_mma_h<<<dim3(EMB / 128, S_LEN / 128), 128, GEMM_SMEM>>>(ctxh, wdh, out, EMB);
}

// round 16
// speedup vs baseline: 1.8684x; 1.0271x over previous
#include <cuda_runtime.h>
#include <cuda_fp16.h>
#include <math_constants.h>
#include <math.h>
#include <cstdint>

// Problem constants
#define S_LEN 2048
#define EMB   2048
#define NH    16
#define NKV   4
#define HD    128
#define FQKV  3072   // NH*HD + 2*NKV*HD
#define GK    2048   // K dim (elements) of BOTH projection GEMMs

// Scratch (device globals: no allocations allowed)
__device__ float  g_qkv[S_LEN * FQKV];        // 25 MB f32 qkv (pre-rope)
__device__ __half g_xh[S_LEN * EMB];          //  8 MB fp16 x
__device__ __half g_wqh[FQKV * EMB];          // 12 MB fp16 w_qkv
__device__ __half g_wdh[EMB * EMB];           //  8 MB fp16 w_dense
__device__ __half g_ctxh[S_LEN * EMB];        //  8 MB fp16 ctx
__device__ __half g_qh[S_LEN * NH * HD];      //  8 MB fp16 roped Q
__device__ __half g_kh[S_LEN * NKV * HD];     //  2 MB fp16 roped K
__device__ __half g_vth[NKV * HD * S_LEN];    //  2 MB fp16 V transposed

// ---------------------------------------------------------------------------
// Helpers
// ---------------------------------------------------------------------------
__device__ __forceinline__ uint32_t smem_u32(const void* p) {
    uint32_t a;
    asm("{ .reg .u64 t; cvta.to.shared.u64 t, %1; cvt.u32.u64 %0, t; }"
        : "=r"(a) : "l"(p));
    return a;
}

// fp16: D += A(16x16) * B(16x8), f32 accum
__device__ __forceinline__ void mma16(float* c, const uint32_t* a,
                                      uint32_t b0, uint32_t b1) {
    asm volatile(
        "mma.sync.aligned.m16n8k16.row.col.f32.f16.f16.f32 "
        "{%0,%1,%2,%3}, {%4,%5,%6,%7}, {%8,%9}, {%0,%1,%2,%3};\n"
        : "+f"(c[0]), "+f"(c[1]), "+f"(c[2]), "+f"(c[3])
        : "r"(a[0]), "r"(a[1]), "r"(a[2]), "r"(a[3]), "r"(b0), "r"(b1));
}

// byte offset of 16B granule (row, g) in an XOR-swizzled tile; gper granules/row
__device__ __forceinline__ uint32_t sw16(int row, int g, int gper) {
    return (uint32_t)(row * gper + (((g ^ row) & 7) | (g & ~7))) * 16;
}

__device__ __forceinline__ void ldm4i(uint32_t* r, uint32_t addr) {
    asm volatile("ldmatrix.sync.aligned.m8n8.x4.shared.b16 {%0,%1,%2,%3}, [%4];"
                 : "=r"(r[0]), "=r"(r[1]), "=r"(r[2]), "=r"(r[3]) : "r"(addr));
}

// fp16 ldmatrix.x4: 16 rows x 16 fp16 cols (k-step kk of 32B) from swizzled tile
__device__ __forceinline__ void ldm4h(uint32_t* r, uint32_t sbase,
                                      int row0, int kk, int gper) {
    int t = threadIdx.x & 31;
    int rr = row0 + (t & 15);
    int gc = 2 * kk + (t >> 4);
    ldm4i(r, sbase + sw16(rr, gc, gper));
}

// fp16 ldmatrix.x4 from padded (unswizzled) fp16 tile, stride in fp16 elems
__device__ __forceinline__ void ldm4hp(uint32_t* r, const __half* base,
                                       int row0, int kk, int stride) {
    int t = threadIdx.x & 31;
    int rr = row0 + (t & 15);
    int cc = kk * 16 + ((t >> 4) << 3);
    ldm4i(r, smem_u32(base + rr * stride + cc));
}

__device__ __forceinline__ void cpasync16(uint32_t dst, const void* src) {
    asm volatile("cp.async.cg.shared.global [%0], [%1], 16;" :: "r"(dst), "l"(src));
}
__device__ __forceinline__ void cpcommit() {
    asm volatile("cp.async.commit_group;");
}

// ---------------------------------------------------------------------------
// f32 -> fp16 (rn) conversion
// ---------------------------------------------------------------------------
__global__ void tohalf_kernel(const float* __restrict__ in,
                              __half* __restrict__ out, int n4) {
    int i = blockIdx.x * blockDim.x + threadIdx.x;
    for (; i < n4; i += gridDim.x * blockDim.x) {
        float4 v = ((const float4*)in)[i];
        ((__half2*)out)[2 * i]     = __floats2half2_rn(v.x, v.y);
        ((__half2*)out)[2 * i + 1] = __floats2half2_rn(v.z, v.w);
    }
}

// ---------------------------------------------------------------------------
// fp16 mma GEMM (unchanged, pass-verified R12/R15): C[m,n]=sum_k A[m,k]*B[n,k].
// Block 128x128, BK=64, 4 warps (64x64), 2-stage cp.async, swizzled smem.
// ---------------------------------------------------------------------------
#define GEMM_SMEM 65536

__device__ __forceinline__ void gemm_issue_h(const __half* __restrict__ A,
                                             const __half* __restrict__ B,
                                             uint32_t sb, int stage,
                                             int bm, int bn, int k0, int tid) {
    uint32_t as = sb + stage * 32768;
    uint32_t bs = as + 16384;
#pragma unroll
    for (int i = 0; i < 8; i++) {
        int idx = i * 128 + tid;
        int row = idx >> 3;
        int g   = idx & 7;
        uint32_t off = sw16(row, g, 8);
        cpasync16(as + off, A + (size_t)(bm + row) * GK + k0 + g * 8);
        cpasync16(bs + off, B + (size_t)(bn + row) * GK + k0 + g * 8);
    }
    cpcommit();
}

__global__ __launch_bounds__(128, 3) void gemm_mma_h(const __half* __restrict__ A,
                                                     const __half* __restrict__ B,
                                                     float* __restrict__ C, int N) {
    extern __shared__ float sm[];
    const uint32_t sb = smem_u32(sm);
    const int tid = threadIdx.x;
    const int lane = tid & 31;
    const int wid = tid >> 5;
    const int bm = blockIdx.y * 128;
    const int bn = blockIdx.x * 128;
    const int wm = (wid >> 1) * 64;
    const int wn = (wid & 1) * 64;

    float acc[4][8][4];
#pragma unroll
    for (int i = 0; i < 4; i++)
#pragma unroll
        for (int j = 0; j < 8; j++)
#pragma unroll
            for (int q = 0; q < 4; q++) acc[i][j][q] = 0.f;

    const int NC = GK / 64;
    gemm_issue_h(A, B, sb, 0, bm, bn, 0, tid);

    for (int c = 0; c < NC; c++) {
        if (c + 1 < NC) {
            gemm_issue_h(A, B, sb, (c + 1) & 1, bm, bn, (c + 1) * 64, tid);
            asm volatile("cp.async.wait_group 1;");
        } else {
            asm volatile("cp.async.wait_group 0;");
        }
        __syncthreads();

        const uint32_t as = sb + (c & 1) * 32768;
        const uint32_t bs = as + 16384;
#pragma unroll
        for (int kk = 0; kk < 4; kk++) {
            uint32_t a[4][4];
#pragma unroll
            for (int mf = 0; mf < 4; mf++)
                ldm4h(a[mf], as, wm + 16 * mf, kk, 8);
#pragma unroll
            for (int nf = 0; nf < 4; nf++) {
                uint32_t b[4];
                ldm4h(b, bs, wn + 16 * nf, kk, 8);
#pragma unroll
                for (int mf = 0; mf < 4; mf++) {
                    mma16(acc[mf][2 * nf],     a[mf], b[0], b[2]);
                    mma16(acc[mf][2 * nf + 1], a[mf], b[1], b[3]);
                }
            }
        }
        __syncthreads();
    }

#pragma unroll
    for (int mf = 0; mf < 4; mf++) {
        int r0 = bm + wm + mf * 16 + (lane >> 2);
#pragma unroll
        for (int nf = 0; nf < 8; nf++) {
            int cc = bn + wn + nf * 8 + 2 * (lane & 3);
            *(float2*)(C + (size_t)r0 * N + cc) =
                make_float2(acc[mf][nf][0], acc[mf][nf][1]);
            *(float2*)(C + (size_t)(r0 + 8) * N + cc) =
                make_float2(acc[mf][nf][2], acc[mf][nf][3]);
        }
    }
}

// ---------------------------------------------------------------------------
// RoPE: read f32 qkv, write fp16 Q -> g_qh[s][h][d], K -> g_kh[s][kvh][d]
// ---------------------------------------------------------------------------
__global__ void rope_kernel() {
    int s    = blockIdx.x;
    int head = blockIdx.y;          // 0..19
    int i    = threadIdx.x;         // 0..63

    size_t off = (size_t)s * FQKV +
                 ((head < NH) ? (size_t)head * HD
                              : (size_t)NH * HD + (size_t)(head - NH) * HD);
    const float* base = g_qkv + off;

    float inv_freq = expf(-(float)(2 * i) * (9.210340371976184f / 128.f));
    float ang = (float)s * inv_freq;
    float c, sn;
    sincosf(ang, &sn, &c);

    float x1 = base[i];
    float x2 = base[i + 64];
    float r1 = x1 * c - x2 * sn;
    float r2 = x2 * c + x1 * sn;

    if (head < NH) {
        __half* dst = g_qh + ((size_t)s * NH + head) * HD;
        dst[i]      = __float2half_rn(r1);
        dst[i + 64] = __float2half_rn(r2);
    } else {
        __half* dst = g_kh + ((size_t)s * NKV + (head - NH)) * HD;
        dst[i]      = __float2half_rn(r1);
        dst[i + 64] = __float2half_rn(r2);
    }
}

// ---------------------------------------------------------------------------
// V transpose: g_vth[kvh*HD + d][s] = fp16(V[s][kvh][d])
// ---------------------------------------------------------------------------
__global__ void vtrans_kernel() {
    __shared__ float t[32][33];
    int kvh = blockIdx.z;
    int s0 = blockIdx.x * 32, d0 = blockIdx.y * 32;
    int tx = threadIdx.x, ty = threadIdx.y;   // 32 x 8
#pragma unroll
    for (int i = 0; i < 32; i += 8)
        t[ty + i][tx] =
            g_qkv[(size_t)(s0 + ty + i) * FQKV + (NH + NKV) * HD + kvh * HD + d0 + tx];
    __syncthreads();
#pragma unroll
    for (int i = 0; i < 32; i += 8)
        g_vth[((size_t)kvh * HD + d0 + ty + i) * S_LEN + s0 + tx] =
            __float2half_rn(t[tx][ty + i]);
}

// ---------------------------------------------------------------------------
// Flash attention, full fp16 mma, 64-row q-tiles, 4 warps (128 thr).
// Per-warp work identical to R15 pass (16 q-rows: S 16x64, PV 16x128);
// 512 CTAs, 2 CTAs/SM (regs+smem fit) -> latency overlap + load balance.
// smem: Qs 64x256B sw (16K) @0, Ks 2x 64x256B sw @16384, V 128x128B sw @49152,
//       Ps fp16[64][72] @65536 -> total 74752 B.
// ---------------------------------------------------------------------------
#define AQ_OFF 0
#define AK_OFF 16384
#define AV_OFF 49152
#define AP_OFF 65536
#define ATT_SMEM 74752
#define PS_STRIDE 72

__global__ __launch_bounds__(128, 2) void flash_attn_mma() {
    extern __shared__ char smc[];
    const uint32_t sb = smem_u32(smc);
    __half* PsH = (__half*)(smc + AP_OFF);

    const int tid = threadIdx.x;
    const int lane = tid & 31;
    const int w = tid >> 5;            // 0..3
    const int h = blockIdx.x;
    const int kvh = h >> 2;
    const int qt = (int)gridDim.y - 1 - (int)blockIdx.y;  // heavy first, 0..31
    const int q0 = qt * 64;
    const float scale = 0.08838834764831845f;   // 1/sqrt(128)

    // prologue: Q + K(0) as one commit group
    {
#pragma unroll
        for (int i = 0; i < 8; i++) {              // Q: 64 rows x 16 granules
            int idx = i * 128 + tid;
            int row = idx >> 4;
            int g   = idx & 15;
            cpasync16(sb + AQ_OFF + sw16(row, g, 16),
                      g_qh + ((size_t)(q0 + row) * NH + h) * HD + g * 8);
        }
#pragma unroll
        for (int i = 0; i < 8; i++) {              // K: 64 rows x 16 granules
            int idx = i * 128 + tid;
            int row = idx >> 4;
            int g   = idx & 15;
            cpasync16(sb + AK_OFF + sw16(row, g, 16),
                      g_kh + ((size_t)row * NKV + kvh) * HD + g * 8);
        }
        cpcommit();
    }

    float m0 = -CUDART_INF_F, m1 = -CUDART_INF_F, l0 = 0.f, l1 = 0.f;
    float o[16][4];
#pragma unroll
    for (int f = 0; f < 16; f++)
#pragma unroll
        for (int q = 0; q < 4; q++) o[f][q] = 0.f;

    const int nkt = qt + 1;
    for (int kt = 0; kt < nkt; kt++) {
        const int k0 = kt * 64;
        __syncthreads();   // prior PV done: Vbuf/Ps safe to overwrite

        // issue V(kt): 128 rows (d) x 8 granules (64 fp16 s-values)
#pragma unroll
        for (int i = 0; i < 8; i++) {
            int idx = i * 128 + tid;
            int row = idx >> 3;
            int g   = idx & 7;
            cpasync16(sb + AV_OFF + sw16(row, g, 8),
                      g_vth + ((size_t)(kvh * HD + row)) * S_LEN + k0 + g * 8);
        }
        cpcommit();

        asm volatile("cp.async.wait_group 1;");  // K(kt) (+Q at kt=0) arrived
        __syncthreads();

        // S = Q K^T : per warp 16x64, 8 k16 steps
        const uint32_t ks = sb + AK_OFF + (uint32_t)(kt & 1) * 16384;
        float s[8][4];
#pragma unroll
        for (int f = 0; f < 8; f++)
#pragma unroll
            for (int q = 0; q < 4; q++) s[f][q] = 0.f;

#pragma unroll 4
        for (int kk = 0; kk < 8; kk++) {
            uint32_t a[4];
            ldm4h(a, sb + AQ_OFF, 16 * w, kk, 16);
#pragma unroll
            for (int j = 0; j < 4; j++) {
                uint32_t b[4];
                ldm4h(b, ks, 16 * j, kk, 16);
                mma16(s[2 * j],     a, b[0], b[2]);
                mma16(s[2 * j + 1], a, b[1], b[3]);
            }
        }

        // mask + scale
        const int r0g = q0 + 16 * w + (lane >> 2);
        const int r1g = r0g + 8;
#pragma unroll
        for (int f = 0; f < 8; f++) {
            int c0g = k0 + 8 * f + 2 * (lane & 3);
            s[f][0] = (c0g     <= r0g) ? s[f][0] * scale : -CUDART_INF_F;
            s[f][1] = (c0g + 1 <= r0g) ? s[f][1] * scale : -CUDART_INF_F;
            s[f][2] = (c0g     <= r1g) ? s[f][2] * scale : -CUDART_INF_F;
            s[f][3] = (c0g + 1 <= r1g) ? s[f][3] * scale : -CUDART_INF_F;
        }

        // online softmax
        float mx0 = -CUDART_INF_F, mx1 = -CUDART_INF_F;
#pragma unroll
        for (int f = 0; f < 8; f++) {
            mx0 = fmaxf(mx0, fmaxf(s[f][0], s[f][1]));
            mx1 = fmaxf(mx1, fmaxf(s[f][2], s[f][3]));
        }
        mx0 = fmaxf(mx0, __shfl_xor_sync(0xffffffffu, mx0, 1));
        mx0 = fmaxf(mx0, __shfl_xor_sync(0xffffffffu, mx0, 2));
        mx1 = fmaxf(mx1, __shfl_xor_sync(0xffffffffu, mx1, 1));
        mx1 = fmaxf(mx1, __shfl_xor_sync(0xffffffffu, mx1, 2));

        float mn0 = fmaxf(m0, mx0), mn1 = fmaxf(m1, mx1);
        float al0 = __expf(m0 - mn0), al1 = __expf(m1 - mn1);
        m0 = mn0; m1 = mn1;

        float rs0 = 0.f, rs1 = 0.f;
#pragma unroll
        for (int f = 0; f < 8; f++) {
            s[f][0] = __expf(s[f][0] - m0);
            s[f][1] = __expf(s[f][1] - m0);
            s[f][2] = __expf(s[f][2] - m1);
            s[f][3] = __expf(s[f][3] - m1);
            rs0 += s[f][0] + s[f][1];
            rs1 += s[f][2] + s[f][3];
        }
        rs0 += __shfl_xor_sync(0xffffffffu, rs0, 1);
        rs0 += __shfl_xor_sync(0xffffffffu, rs0, 2);
        rs1 += __shfl_xor_sync(0xffffffffu, rs1, 1);
        rs1 += __shfl_xor_sync(0xffffffffu, rs1, 2);
        l0 = l0 * al0 + rs0;
        l1 = l1 * al1 + rs1;

#pragma unroll
        for (int f = 0; f < 16; f++) {
            o[f][0] *= al0; o[f][1] *= al0;
            o[f][2] *= al1; o[f][3] *= al1;
        }

        // P -> Ps fp16, warp-private rows
        const int lr0 = 16 * w + (lane >> 2);
#pragma unroll
        for (int f = 0; f < 8; f++) {
            int cc = 8 * f + 2 * (lane & 3);
            *(__half2*)(PsH + lr0 * PS_STRIDE + cc) =
                __floats2half2_rn(s[f][0], s[f][1]);
            *(__half2*)(PsH + (lr0 + 8) * PS_STRIDE + cc) =
                __floats2half2_rn(s[f][2], s[f][3]);
        }
        __syncwarp();

        // prefetch K(kt+1), then ensure V(kt) arrived
        if (kt + 1 < nkt) {
            const int nk0 = (kt + 1) * 64;
            const uint32_t kd = sb + AK_OFF + (uint32_t)((kt + 1) & 1) * 16384;
#pragma unroll
            for (int i = 0; i < 8; i++) {
                int idx = i * 128 + tid;
                int row = idx >> 4;
                int g   = idx & 15;
                cpasync16(kd + sw16(row, g, 16),
                          g_kh + ((size_t)(nk0 + row) * NKV + kvh) * HD + g * 8);
            }
            cpcommit();
            asm volatile("cp.async.wait_group 1;");   // V(kt) done
        } else {
            asm volatile("cp.async.wait_group 0;");
        }
        __syncthreads();

        // O += P V : per warp 16x128, 4 k16 steps
#pragma unroll 2
        for (int kk = 0; kk < 4; kk++) {
            uint32_t a[4];
            ldm4hp(a, PsH, 16 * w, kk, PS_STRIDE);
#pragma unroll
            for (int j = 0; j < 8; j++) {
                uint32_t b[4];
                ldm4h(b, sb + AV_OFF, 16 * j, kk, 8);
                mma16(o[2 * j],     a, b[0], b[2]);
                mma16(o[2 * j + 1], a, b[1], b[3]);
            }
        }
    }

    // epilogue: normalize, write fp16 ctx
    const float inv0 = 1.f / l0, inv1 = 1.f / l1;
    const int gr0 = q0 + 16 * w + (lane >> 2);
    const int gr1 = gr0 + 8;
#pragma unroll
    for (int f = 0; f < 16; f++) {
        int cc = h * HD + 8 * f + 2 * (lane & 3);
        *(__half2*)(g_ctxh + (size_t)gr0 * EMB + cc) =
            __floats2half2_rn(o[f][0] * inv0, o[f][1] * inv0);
        *(__half2*)(g_ctxh + (size_t)gr1 * EMB + cc) =
            __floats2half2_rn(o[f][2] * inv1, o[f][3] * inv1);
    }
}

// ---------------------------------------------------------------------------
// Launch
// ---------------------------------------------------------------------------
extern "C" void kernel_launch(void* const* d_in, const int* in_sizes, int n_in,
                              void* d_out, int out_size)
{
    const float* x       = (const float*)d_in[0];
    const float* w_qkv   = (const float*)d_in[1];
    const float* w_dense = (const float*)d_in[2];
    float* out = (float*)d_out;

    float *qkv;
    __half *xh, *wqh, *wdh, *ctxh;
    cudaGetSymbolAddress((void**)&qkv,  g_qkv);
    cudaGetSymbolAddress((void**)&xh,   g_xh);
    cudaGetSymbolAddress((void**)&wqh,  g_wqh);
    cudaGetSymbolAddress((void**)&wdh,  g_wdh);
    cudaGetSymbolAddress((void**)&ctxh, g_ctxh);

    cudaFuncSetAttribute(gemm_mma_h, cudaFuncAttributeMaxDynamicSharedMemorySize, GEMM_SMEM);
    cudaFuncSetAttribute(flash_attn_mma, cudaFuncAttributeMaxDynamicSharedMemorySize, ATT_SMEM);

    // 0) fp16 conversions
    tohalf_kernel<<<512, 256>>>(x,       xh,  S_LEN * EMB / 4);
    tohalf_kernel<<<512, 256>>>(w_qkv,   wqh, FQKV * EMB / 4);
    tohalf_kernel<<<512, 256>>>(w_dense, wdh, EMB * EMB / 4);

    // 1) qkv = x @ w_qkv^T   (fp16 mma, f32 out)
    gemm_mma_h<<<dim3(FQKV / 128, S_LEN / 128), 128, GEMM_SMEM>>>(xh, wqh, qkv, FQKV);
    // 2) RoPE -> fp16 Q/K
    rope_kernel<<<dim3(S_LEN, NH + NKV), 64>>>();
    // 3) V transpose -> fp16
    vtrans_kernel<<<dim3(S_LEN / 32, HD / 32, NKV), dim3(32, 8)>>>();
    // 4) causal GQA flash attention (fp16 mma, 64-row q-tiles) -> fp16 ctx
    flash_attn_mma<<<dim3(NH, S_LEN / 64), 128, ATT_SMEM>>>();
    // 5) out = ctx @ w_dense^T  (fp16 mma, f32 out)
    gemm_mma_h<<<dim3(EMB / 128, S_LEN / 128), 128, GEMM_SMEM>>>(ctxh, wdh, out, EMB);
}

// round 17
// speedup vs baseline: 1.9774x; 1.0584x over previous
#include <cuda_runtime.h>
#include <cuda_fp16.h>
#include <math_constants.h>
#include <math.h>
#include <cstdint>

// Problem constants
#define S_LEN 2048
#define EMB   2048
#define NH    16
#define NKV   4
#define HD    128
#define FQKV  3072   // NH*HD + 2*NKV*HD
#define GK    2048   // K dim (elements) of BOTH projection GEMMs

// Scratch (device globals: no allocations allowed)
__device__ float  g_qkv[S_LEN * FQKV];        // 25 MB f32 qkv (pre-rope)
__device__ __half g_xh[S_LEN * EMB];          //  8 MB fp16 x
__device__ __half g_wqh[FQKV * EMB];          // 12 MB fp16 w_qkv
__device__ __half g_wdh[EMB * EMB];           //  8 MB fp16 w_dense
__device__ __half g_ctxh[S_LEN * EMB];        //  8 MB fp16 ctx
__device__ __half g_qh[S_LEN * NH * HD];      //  8 MB fp16 roped Q
__device__ __half g_kh[S_LEN * NKV * HD];     //  2 MB fp16 roped K
__device__ __half g_vth[NKV * HD * S_LEN];    //  2 MB fp16 V transposed

// ---------------------------------------------------------------------------
// Helpers
// ---------------------------------------------------------------------------
__device__ __forceinline__ uint32_t smem_u32(const void* p) {
    uint32_t a;
    asm("{ .reg .u64 t; cvta.to.shared.u64 t, %1; cvt.u32.u64 %0, t; }"
        : "=r"(a) : "l"(p));
    return a;
}

// fp16: D += A(16x16) * B(16x8), f32 accum
__device__ __forceinline__ void mma16(float* c, const uint32_t* a,
                                      uint32_t b0, uint32_t b1) {
    asm volatile(
        "mma.sync.aligned.m16n8k16.row.col.f32.f16.f16.f32 "
        "{%0,%1,%2,%3}, {%4,%5,%6,%7}, {%8,%9}, {%0,%1,%2,%3};\n"
        : "+f"(c[0]), "+f"(c[1]), "+f"(c[2]), "+f"(c[3])
        : "r"(a[0]), "r"(a[1]), "r"(a[2]), "r"(a[3]), "r"(b0), "r"(b1));
}

// byte offset of 16B granule (row, g) in an XOR-swizzled tile; gper granules/row
__device__ __forceinline__ uint32_t sw16(int row, int g, int gper) {
    return (uint32_t)(row * gper + (((g ^ row) & 7) | (g & ~7))) * 16;
}

__device__ __forceinline__ void ldm4i(uint32_t* r, uint32_t addr) {
    asm volatile("ldmatrix.sync.aligned.m8n8.x4.shared.b16 {%0,%1,%2,%3}, [%4];"
                 : "=r"(r[0]), "=r"(r[1]), "=r"(r[2]), "=r"(r[3]) : "r"(addr));
}

// fp16 ldmatrix.x4: 16 rows x 16 fp16 cols (k-step kk of 32B) from swizzled tile
__device__ __forceinline__ void ldm4h(uint32_t* r, uint32_t sbase,
                                      int row0, int kk, int gper) {
    int t = threadIdx.x & 31;
    int rr = row0 + (t & 15);
    int gc = 2 * kk + (t >> 4);
    ldm4i(r, sbase + sw16(rr, gc, gper));
}

// fp16 ldmatrix.x4 from padded (unswizzled) fp16 tile, stride in fp16 elems
__device__ __forceinline__ void ldm4hp(uint32_t* r, const __half* base,
                                       int row0, int kk, int stride) {
    int t = threadIdx.x & 31;
    int rr = row0 + (t & 15);
    int cc = kk * 16 + ((t >> 4) << 3);
    ldm4i(r, smem_u32(base + rr * stride + cc));
}

__device__ __forceinline__ void cpasync16(uint32_t dst, const void* src) {
    asm volatile("cp.async.cg.shared.global [%0], [%1], 16;" :: "r"(dst), "l"(src));
}
__device__ __forceinline__ void cpcommit() {
    asm volatile("cp.async.commit_group;");
}

// ---------------------------------------------------------------------------
// f32 -> fp16 (rn) conversion
// ---------------------------------------------------------------------------
__global__ void tohalf_kernel(const float* __restrict__ in,
                              __half* __restrict__ out, int n4) {
    int i = blockIdx.x * blockDim.x + threadIdx.x;
    for (; i < n4; i += gridDim.x * blockDim.x) {
        float4 v = ((const float4*)in)[i];
        ((__half2*)out)[2 * i]     = __floats2half2_rn(v.x, v.y);
        ((__half2*)out)[2 * i + 1] = __floats2half2_rn(v.z, v.w);
    }
}

// ---------------------------------------------------------------------------
// fp16 mma GEMM, 3-stage pipeline, ONE barrier per chunk.
// C[m,n] = sum_k A[m,k]*B[n,k]. Block 128x128, BK=64, 4 warps (64x64 tile).
// smem: 3 stages x (A 16KB + B 16KB) = 96KB -> 2 CTAs/SM.
// Invariant at iter c top: groups {c, c+1} in flight; wait_group 1 -> c done.
// issue(c+2) overwrites stage (c-1)%3, retired by the barrier.
// ---------------------------------------------------------------------------
#define GEMM_SMEM 98304

__device__ __forceinline__ void gemm_issue_h(const __half* __restrict__ A,
                                             const __half* __restrict__ B,
                                             uint32_t sb, int stage,
                                             int bm, int bn, int k0, int tid) {
    uint32_t as = sb + stage * 32768;
    uint32_t bs = as + 16384;
#pragma unroll
    for (int i = 0; i < 8; i++) {
        int idx = i * 128 + tid;
        int row = idx >> 3;
        int g   = idx & 7;
        uint32_t off = sw16(row, g, 8);
        cpasync16(as + off, A + (size_t)(bm + row) * GK + k0 + g * 8);
        cpasync16(bs + off, B + (size_t)(bn + row) * GK + k0 + g * 8);
    }
    cpcommit();
}

__global__ __launch_bounds__(128, 2) void gemm_mma_h(const __half* __restrict__ A,
                                                     const __half* __restrict__ B,
                                                     float* __restrict__ C, int N) {
    extern __shared__ float sm[];
    const uint32_t sb = smem_u32(sm);
    const int tid = threadIdx.x;
    const int lane = tid & 31;
    const int wid = tid >> 5;
    const int bm = blockIdx.y * 128;
    const int bn = blockIdx.x * 128;
    const int wm = (wid >> 1) * 64;
    const int wn = (wid & 1) * 64;

    float acc[4][8][4];
#pragma unroll
    for (int i = 0; i < 4; i++)
#pragma unroll
        for (int j = 0; j < 8; j++)
#pragma unroll
            for (int q = 0; q < 4; q++) acc[i][j][q] = 0.f;

    const int NC = GK / 64;            // 32 chunks
    gemm_issue_h(A, B, sb, 0, bm, bn, 0, tid);
    gemm_issue_h(A, B, sb, 1, bm, bn, 64, tid);

    int s_cur = 0;   // stage of chunk c
    int s_nxt = 2;   // stage of chunk c+2
    for (int c = 0; c < NC; c++) {
        if (c + 1 < NC) asm volatile("cp.async.wait_group 1;");
        else            asm volatile("cp.async.wait_group 0;");
        __syncthreads();

        if (c + 2 < NC)
            gemm_issue_h(A, B, sb, s_nxt, bm, bn, (c + 2) * 64, tid);

        const uint32_t as = sb + (uint32_t)s_cur * 32768;
        const uint32_t bs = as + 16384;
#pragma unroll
        for (int kk = 0; kk < 4; kk++) {
            uint32_t a[4][4];
#pragma unroll
            for (int mf = 0; mf < 4; mf++)
                ldm4h(a[mf], as, wm + 16 * mf, kk, 8);
#pragma unroll
            for (int nf = 0; nf < 4; nf++) {
                uint32_t b[4];
                ldm4h(b, bs, wn + 16 * nf, kk, 8);
#pragma unroll
                for (int mf = 0; mf < 4; mf++) {
                    mma16(acc[mf][2 * nf],     a[mf], b[0], b[2]);
                    mma16(acc[mf][2 * nf + 1], a[mf], b[1], b[3]);
                }
            }
        }
        s_cur = (s_cur == 2) ? 0 : s_cur + 1;
        s_nxt = (s_nxt == 2) ? 0 : s_nxt + 1;
    }

#pragma unroll
    for (int mf = 0; mf < 4; mf++) {
        int r0 = bm + wm + mf * 16 + (lane >> 2);
#pragma unroll
        for (int nf = 0; nf < 8; nf++) {
            int cc = bn + wn + nf * 8 + 2 * (lane & 3);
            *(float2*)(C + (size_t)r0 * N + cc) =
                make_float2(acc[mf][nf][0], acc[mf][nf][1]);
            *(float2*)(C + (size_t)(r0 + 8) * N + cc) =
                make_float2(acc[mf][nf][2], acc[mf][nf][3]);
        }
    }
}

// ---------------------------------------------------------------------------
// RoPE: read f32 qkv, write fp16 Q -> g_qh[s][h][d], K -> g_kh[s][kvh][d]
// ---------------------------------------------------------------------------
__global__ void rope_kernel() {
    int s    = blockIdx.x;
    int head = blockIdx.y;          // 0..19
    int i    = threadIdx.x;         // 0..63

    size_t off = (size_t)s * FQKV +
                 ((head < NH) ? (size_t)head * HD
                              : (size_t)NH * HD + (size_t)(head - NH) * HD);
    const float* base = g_qkv + off;

    float inv_freq = expf(-(float)(2 * i) * (9.210340371976184f / 128.f));
    float ang = (float)s * inv_freq;
    float c, sn;
    sincosf(ang, &sn, &c);

    float x1 = base[i];
    float x2 = base[i + 64];
    float r1 = x1 * c - x2 * sn;
    float r2 = x2 * c + x1 * sn;

    if (head < NH) {
        __half* dst = g_qh + ((size_t)s * NH + head) * HD;
        dst[i]      = __float2half_rn(r1);
        dst[i + 64] = __float2half_rn(r2);
    } else {
        __half* dst = g_kh + ((size_t)s * NKV + (head - NH)) * HD;
        dst[i]      = __float2half_rn(r1);
        dst[i + 64] = __float2half_rn(r2);
    }
}

// ---------------------------------------------------------------------------
// V transpose: g_vth[kvh*HD + d][s] = fp16(V[s][kvh][d])
// ---------------------------------------------------------------------------
__global__ void vtrans_kernel() {
    __shared__ float t[32][33];
    int kvh = blockIdx.z;
    int s0 = blockIdx.x * 32, d0 = blockIdx.y * 32;
    int tx = threadIdx.x, ty = threadIdx.y;   // 32 x 8
#pragma unroll
    for (int i = 0; i < 32; i += 8)
        t[ty + i][tx] =
            g_qkv[(size_t)(s0 + ty + i) * FQKV + (NH + NKV) * HD + kvh * HD + d0 + tx];
    __syncthreads();
#pragma unroll
    for (int i = 0; i < 32; i += 8)
        g_vth[((size_t)kvh * HD + d0 + ty + i) * S_LEN + s0 + tx] =
            __float2half_rn(t[tx][ty + i]);
}

// ---------------------------------------------------------------------------
// Flash attention (unchanged, pass-verified R16): fp16 mma, 64-row q-tiles,
// 4 warps, 2 CTAs/SM. smem total 74752 B.
// ---------------------------------------------------------------------------
#define AQ_OFF 0
#define AK_OFF 16384
#define AV_OFF 49152
#define AP_OFF 65536
#define ATT_SMEM 74752
#define PS_STRIDE 72

__global__ __launch_bounds__(128, 2) void flash_attn_mma() {
    extern __shared__ char smc[];
    const uint32_t sb = smem_u32(smc);
    __half* PsH = (__half*)(smc + AP_OFF);

    const int tid = threadIdx.x;
    const int lane = tid & 31;
    const int w = tid >> 5;            // 0..3
    const int h = blockIdx.x;
    const int kvh = h >> 2;
    const int qt = (int)gridDim.y - 1 - (int)blockIdx.y;  // heavy first, 0..31
    const int q0 = qt * 64;
    const float scale = 0.08838834764831845f;   // 1/sqrt(128)

    // prologue: Q + K(0) as one commit group
    {
#pragma unroll
        for (int i = 0; i < 8; i++) {              // Q: 64 rows x 16 granules
            int idx = i * 128 + tid;
            int row = idx >> 4;
            int g   = idx & 15;
            cpasync16(sb + AQ_OFF + sw16(row, g, 16),
                      g_qh + ((size_t)(q0 + row) * NH + h) * HD + g * 8);
        }
#pragma unroll
        for (int i = 0; i < 8; i++) {              // K: 64 rows x 16 granules
            int idx = i * 128 + tid;
            int row = idx >> 4;
            int g   = idx & 15;
            cpasync16(sb + AK_OFF + sw16(row, g, 16),
                      g_kh + ((size_t)row * NKV + kvh) * HD + g * 8);
        }
        cpcommit();
    }

    float m0 = -CUDART_INF_F, m1 = -CUDART_INF_F, l0 = 0.f, l1 = 0.f;
    float o[16][4];
#pragma unroll
    for (int f = 0; f < 16; f++)
#pragma unroll
        for (int q = 0; q < 4; q++) o[f][q] = 0.f;

    const int nkt = qt + 1;
    for (int kt = 0; kt < nkt; kt++) {
        const int k0 = kt * 64;
        __syncthreads();   // prior PV done: Vbuf/Ps safe to overwrite

        // issue V(kt): 128 rows (d) x 8 granules (64 fp16 s-values)
#pragma unroll
        for (int i = 0; i < 8; i++) {
            int idx = i * 128 + tid;
            int row = idx >> 3;
            int g   = idx & 7;
            cpasync16(sb + AV_OFF + sw16(row, g, 8),
                      g_vth + ((size_t)(kvh * HD + row)) * S_LEN + k0 + g * 8);
        }
        cpcommit();

        asm volatile("cp.async.wait_group 1;");  // K(kt) (+Q at kt=0) arrived
        __syncthreads();

        // S = Q K^T : per warp 16x64, 8 k16 steps
        const uint32_t ks = sb + AK_OFF + (uint32_t)(kt & 1) * 16384;
        float s[8][4];
#pragma unroll
        for (int f = 0; f < 8; f++)
#pragma unroll
            for (int q = 0; q < 4; q++) s[f][q] = 0.f;

#pragma unroll 4
        for (int kk = 0; kk < 8; kk++) {
            uint32_t a[4];
            ldm4h(a, sb + AQ_OFF, 16 * w, kk, 16);
#pragma unroll
            for (int j = 0; j < 4; j++) {
                uint32_t b[4];
                ldm4h(b, ks, 16 * j, kk, 16);
                mma16(s[2 * j],     a, b[0], b[2]);
                mma16(s[2 * j + 1], a, b[1], b[3]);
            }
        }

        // mask + scale
        const int r0g = q0 + 16 * w + (lane >> 2);
        const int r1g = r0g + 8;
#pragma unroll
        for (int f = 0; f < 8; f++) {
            int c0g = k0 + 8 * f + 2 * (lane & 3);
            s[f][0] = (c0g     <= r0g) ? s[f][0] * scale : -CUDART_INF_F;
            s[f][1] = (c0g + 1 <= r0g) ? s[f][1] * scale : -CUDART_INF_F;
            s[f][2] = (c0g     <= r1g) ? s[f][2] * scale : -CUDART_INF_F;
            s[f][3] = (c0g + 1 <= r1g) ? s[f][3] * scale : -CUDART_INF_F;
        }

        // online softmax
        float mx0 = -CUDART_INF_F, mx1 = -CUDART_INF_F;
#pragma unroll
        for (int f = 0; f < 8; f++) {
            mx0 = fmaxf(mx0, fmaxf(s[f][0], s[f][1]));
            mx1 = fmaxf(mx1, fmaxf(s[f][2], s[f][3]));
        }
        mx0 = fmaxf(mx0, __shfl_xor_sync(0xffffffffu, mx0, 1));
        mx0 = fmaxf(mx0, __shfl_xor_sync(0xffffffffu, mx0, 2));
        mx1 = fmaxf(mx1, __shfl_xor_sync(0xffffffffu, mx1, 1));
        mx1 = fmaxf(mx1, __shfl_xor_sync(0xffffffffu, mx1, 2));

        float mn0 = fmaxf(m0, mx0), mn1 = fmaxf(m1, mx1);
        float al0 = __expf(m0 - mn0), al1 = __expf(m1 - mn1);
        m0 = mn0; m1 = mn1;

        float rs0 = 0.f, rs1 = 0.f;
#pragma unroll
        for (int f = 0; f < 8; f++) {
            s[f][0] = __expf(s[f][0] - m0);
            s[f][1] = __expf(s[f][1] - m0);
            s[f][2] = __expf(s[f][2] - m1);
            s[f][3] = __expf(s[f][3] - m1);
            rs0 += s[f][0] + s[f][1];
            rs1 += s[f][2] + s[f][3];
        }
        rs0 += __shfl_xor_sync(0xffffffffu, rs0, 1);
        rs0 += __shfl_xor_sync(0xffffffffu, rs0, 2);
        rs1 += __shfl_xor_sync(0xffffffffu, rs1, 1);
        rs1 += __shfl_xor_sync(0xffffffffu, rs1, 2);
        l0 = l0 * al0 + rs0;
        l1 = l1 * al1 + rs1;

#pragma unroll
        for (int f = 0; f < 16; f++) {
            o[f][0] *= al0; o[f][1] *= al0;
            o[f][2] *= al1; o[f][3] *= al1;
        }

        // P -> Ps fp16, warp-private rows
        const int lr0 = 16 * w + (lane >> 2);
#pragma unroll
        for (int f = 0; f < 8; f++) {
            int cc = 8 * f + 2 * (lane & 3);
            *(__half2*)(PsH + lr0 * PS_STRIDE + cc) =
                __floats2half2_rn(s[f][0], s[f][1]);
            *(__half2*)(PsH + (lr0 + 8) * PS_STRIDE + cc) =
                __floats2half2_rn(s[f][2], s[f][3]);
        }
        __syncwarp();

        // prefetch K(kt+1), then ensure V(kt) arrived
        if (kt + 1 < nkt) {
            const int nk0 = (kt + 1) * 64;
            const uint32_t kd = sb + AK_OFF + (uint32_t)((kt + 1) & 1) * 16384;
#pragma unroll
            for (int i = 0; i < 8; i++) {
                int idx = i * 128 + tid;
                int row = idx >> 4;
                int g   = idx & 15;
                cpasync16(kd + sw16(row, g, 16),
                          g_kh + ((size_t)(nk0 + row) * NKV + kvh) * HD + g * 8);
            }
            cpcommit();
            asm volatile("cp.async.wait_group 1;");   // V(kt) done
        } else {
            asm volatile("cp.async.wait_group 0;");
        }
        __syncthreads();

        // O += P V : per warp 16x128, 4 k16 steps
#pragma unroll 2
        for (int kk = 0; kk < 4; kk++) {
            uint32_t a[4];
            ldm4hp(a, PsH, 16 * w, kk, PS_STRIDE);
#pragma unroll
            for (int j = 0; j < 8; j++) {
                uint32_t b[4];
                ldm4h(b, sb + AV_OFF, 16 * j, kk, 8);
                mma16(o[2 * j],     a, b[0], b[2]);
                mma16(o[2 * j + 1], a, b[1], b[3]);
            }
        }
    }

    // epilogue: normalize, write fp16 ctx
    const float inv0 = 1.f / l0, inv1 = 1.f / l1;
    const int gr0 = q0 + 16 * w + (lane >> 2);
    const int gr1 = gr0 + 8;
#pragma unroll
    for (int f = 0; f < 16; f++) {
        int cc = h * HD + 8 * f + 2 * (lane & 3);
        *(__half2*)(g_ctxh + (size_t)gr0 * EMB + cc) =
            __floats2half2_rn(o[f][0] * inv0, o[f][1] * inv0);
        *(__half2*)(g_ctxh + (size_t)gr1 * EMB + cc) =
            __floats2half2_rn(o[f][2] * inv1, o[f][3] * inv1);
    }
}

// ---------------------------------------------------------------------------
// Launch
// ---------------------------------------------------------------------------
extern "C" void kernel_launch(void* const* d_in, const int* in_sizes, int n_in,
                              void* d_out, int out_size)
{
    const float* x       = (const float*)d_in[0];
    const float* w_qkv   = (const float*)d_in[1];
    const float* w_dense = (const float*)d_in[2];
    float* out = (float*)d_out;

    float *qkv;
    __half *xh, *wqh, *wdh, *ctxh;
    cudaGetSymbolAddress((void**)&qkv,  g_qkv);
    cudaGetSymbolAddress((void**)&xh,   g_xh);
    cudaGetSymbolAddress((void**)&wqh,  g_wqh);
    cudaGetSymbolAddress((void**)&wdh,  g_wdh);
    cudaGetSymbolAddress((void**)&ctxh, g_ctxh);

    cudaFuncSetAttribute(gemm_mma_h, cudaFuncAttributeMaxDynamicSharedMemorySize, GEMM_SMEM);
    cudaFuncSetAttribute(flash_attn_mma, cudaFuncAttributeMaxDynamicSharedMemorySize, ATT_SMEM);

    // 0) fp16 conversions
    tohalf_kernel<<<512, 256>>>(x,       xh,  S_LEN * EMB / 4);
    tohalf_kernel<<<512, 256>>>(w_qkv,   wqh, FQKV * EMB / 4);
    tohalf_kernel<<<512, 256>>>(w_dense, wdh, EMB * EMB / 4);

    // 1) qkv = x @ w_qkv^T   (fp16 mma, f32 out)
    gemm_mma_h<<<dim3(FQKV / 128, S_LEN / 128), 128, GEMM_SMEM>>>(xh, wqh, qkv, FQKV);
    // 2) RoPE -> fp16 Q/K
    rope_kernel<<<dim3(S_LEN, NH + NKV), 64>>>();
    // 3) V transpose -> fp16
    vtrans_kernel<<<dim3(S_LEN / 32, HD / 32, NKV), dim3(32, 8)>>>();
    // 4) causal GQA flash attention (fp16 mma, 64-row q-tiles) -> fp16 ctx
    flash_attn_mma<<<dim3(NH, S_LEN / 64), 128, ATT_SMEM>>>();
    // 5) out = ctx @ w_dense^T  (fp16 mma, f32 out)
    gemm_mma_h<<<dim3(EMB / 128, S_LEN / 128), 128, GEMM_SMEM>>>(ctxh, wdh, out, EMB);
}